// round 1
// baseline (speedup 1.0000x reference)
#include <cuda_runtime.h>

#define NPTS 80000
#define NSAMP 16
#define PAIRS (NPTS*NSAMP)
#define EPSF 1e-5f

// ---------------- scratch (device-global; no allocations allowed) -------------
// layout (floats):
//   t1   [N*64]      x@W1
//   q    [N*64]
//   k    [N*64]
//   v    [N*64]
//   w1b  [N*16*8]    intermediate attention weights (after Ww1+bw1)
//   agg  [N*64]
//   t3   [N*64]
//   stats[544]       atomically-accumulated sums/sumsq (zeroed each launch)
//   prm  [544]       finalized bn scale/shift pairs (same sublayout as stats)
#define OFF_T1    0
#define OFF_Q     5120000
#define OFF_K     10240000
#define OFF_V     15360000
#define OFF_W1B   20480000
#define OFF_AGG   30720000
#define OFF_T3    35840000
#define OFF_STATS 40960000
#define OFF_PRM   40960544
__device__ float g_scr[40961088];

// stats/prm sublayout (float offsets):
//  +0   bn1  (64)   | +64  bn1  (64)
//  +128 bnp  (3,pad)| +136 bnp  (3,pad)
//  +144 bnw1 (64)   | +208 bnw1 (64)
//  +272 bnw2 (8)    | +280 bnw2 (8)
//  +288 bn2  (64)   | +352 bn2  (64)
//  +416 bn3  (64)   | +480 bn3  (64)

// ---------------------------------------------------------------------------
__global__ void k_zero(float* st) { int i = threadIdx.x; if (i < 544) st[i] = 0.f; }

// out[n,c] = (optional relu(in*a+c)) row of X @ W   ; 64x64 weights, tile 64 rows
template<bool IN_BN>
__global__ void k_gemm64(const float* __restrict__ X, const float* __restrict__ W,
                         const float* __restrict__ inA, const float* __restrict__ inC,
                         float* __restrict__ out)
{
    __shared__ float sX[64][65];
    __shared__ float sW[64][64];
    const int tid = threadIdx.x;
    const long row0 = (long)blockIdx.x * 64;
    for (int i = tid; i < 4096; i += 256) sW[i >> 6][i & 63] = W[i];
    for (int i = tid; i < 4096; i += 256) {
        int r = i >> 6, kk = i & 63;
        float val = X[(row0 + r) * 64 + kk];
        if (IN_BN) val = fmaxf(fmaf(val, __ldg(&inA[kk]), __ldg(&inC[kk])), 0.f);
        sX[r][kk] = val;
    }
    __syncthreads();
    const int r = tid & 63, c0 = (tid >> 6) << 4;
    float acc[16];
#pragma unroll
    for (int j = 0; j < 16; j++) acc[j] = 0.f;
#pragma unroll
    for (int kk = 0; kk < 64; kk++) {
        float xv = sX[r][kk];
#pragma unroll
        for (int j = 0; j < 16; j++) acc[j] = fmaf(xv, sW[kk][c0 + j], acc[j]);
    }
    float* op = out + (row0 + r) * 64 + c0;
#pragma unroll
    for (int j = 0; j < 16; j++) op[j] = acc[j];
}

// q/k/v fused: t1 tile loaded once (with bn1+relu), 3 weight matrices streamed
__global__ void k_qkv(const float* __restrict__ T1,
                      const float* __restrict__ Wq, const float* __restrict__ bq,
                      const float* __restrict__ Wk, const float* __restrict__ bk,
                      const float* __restrict__ Wv, const float* __restrict__ bv,
                      const float* __restrict__ a1, const float* __restrict__ c1,
                      float* __restrict__ oq, float* __restrict__ ok, float* __restrict__ ov)
{
    __shared__ float sX[64][65];
    __shared__ float sW[64][64];
    const int tid = threadIdx.x;
    const long row0 = (long)blockIdx.x * 64;
    for (int i = tid; i < 4096; i += 256) {
        int r = i >> 6, kk = i & 63;
        sX[r][kk] = fmaxf(fmaf(T1[(row0 + r) * 64 + kk], __ldg(&a1[kk]), __ldg(&c1[kk])), 0.f);
    }
    const int r = tid & 63, c0 = (tid >> 6) << 4;
    const float* Ws[3] = {Wq, Wk, Wv};
    const float* Bs[3] = {bq, bk, bv};
    float* Os[3] = {oq, ok, ov};
#pragma unroll 1
    for (int m = 0; m < 3; m++) {
        __syncthreads();
        for (int i = tid; i < 4096; i += 256) sW[i >> 6][i & 63] = Ws[m][i];
        __syncthreads();
        float acc[16];
#pragma unroll
        for (int j = 0; j < 16; j++) acc[j] = __ldg(&Bs[m][c0 + j]);
#pragma unroll
        for (int kk = 0; kk < 64; kk++) {
            float xv = sX[r][kk];
#pragma unroll
            for (int j = 0; j < 16; j++) acc[j] = fmaf(xv, sW[kk][c0 + j], acc[j]);
        }
        float* op = Os[m] + (row0 + r) * 64 + c0;
#pragma unroll
        for (int j = 0; j < 16; j++) op[j] = acc[j];
    }
}

// per-column sum & sumsq of an (nrows x NC) row-major array
template<int NC>
__global__ void k_colstats(const float* __restrict__ X, int nrows,
                           float* __restrict__ sumB, float* __restrict__ sqB)
{
    const int RPB = 256 / NC;
    const int c = threadIdx.x % NC;
    const int rs = threadIdx.x / NC;
    float s = 0.f, q = 0.f;
    for (long r = (long)blockIdx.x * RPB + rs; r < nrows; r += (long)gridDim.x * RPB) {
        float val = X[r * NC + c];
        s += val; q = fmaf(val, val, q);
    }
    __shared__ float sS[256], sQ[256];
    sS[threadIdx.x] = s; sQ[threadIdx.x] = q;
    __syncthreads();
    if (threadIdx.x < NC) {
        float ts = 0.f, tq = 0.f;
        for (int i = threadIdx.x; i < 256; i += NC) { ts += sS[i]; tq += sQ[i]; }
        atomicAdd(&sumB[c], ts); atomicAdd(&sqB[c], tq);
    }
}

__global__ void k_finalize(const float* __restrict__ sum, const float* __restrict__ sq,
                           const float* __restrict__ g, const float* __restrict__ b,
                           float invN, float* a, float* c, int nch)
{
    int i = threadIdx.x;
    if (i < nch) {
        float m = sum[i] * invN;
        float var = fmaf(-m, m, sq[i] * invN);
        float aa = g[i] * rsqrtf(var + EPSF);
        a[i] = aa;
        c[i] = fmaf(-m, aa, b[i]);
    }
}

// constants for the positional-encoding mini-MLP (3->3 bn relu ->64)
struct PeC {
    float w0,w1,w2,w3,w4,w5,w6,w7,w8,b0,b1,b2,A0,A1,A2,C0,C1,C2;
    __device__ __forceinline__ void load(const float* Wp1, const float* bp1,
                                         const float* pa, const float* pc) {
        w0=__ldg(&Wp1[0]); w1=__ldg(&Wp1[1]); w2=__ldg(&Wp1[2]);
        w3=__ldg(&Wp1[3]); w4=__ldg(&Wp1[4]); w5=__ldg(&Wp1[5]);
        w6=__ldg(&Wp1[6]); w7=__ldg(&Wp1[7]); w8=__ldg(&Wp1[8]);
        b0=__ldg(&bp1[0]); b1=__ldg(&bp1[1]); b2=__ldg(&bp1[2]);
        A0=__ldg(&pa[0]);  A1=__ldg(&pa[1]);  A2=__ldg(&pa[2]);
        C0=__ldg(&pc[0]);  C1=__ldg(&pc[1]);  C2=__ldg(&pc[2]);
    }
    __device__ __forceinline__ void rel(float ax, float ay, float az,
                                        float& r0, float& r1, float& r2) const {
        r0 = fmaxf(fmaf(fmaf(ax,w0,fmaf(ay,w3,fmaf(az,w6,b0))), A0, C0), 0.f);
        r1 = fmaxf(fmaf(fmaf(ax,w1,fmaf(ay,w4,fmaf(az,w7,b1))), A1, C1), 0.f);
        r2 = fmaxf(fmaf(fmaf(ax,w2,fmaf(ay,w5,fmaf(az,w8,b2))), A2, C2), 0.f);
    }
};

// stats for bn of (p_r @ Wp1 + bp1): 3 channels over PAIRS
__global__ void k_pstats(const float* __restrict__ p, const int* __restrict__ knn,
                         const float* __restrict__ Wp1, const float* __restrict__ bp1,
                         float* __restrict__ st)
{
    float w[9], bb[3];
#pragma unroll
    for (int i = 0; i < 9; i++) w[i] = __ldg(&Wp1[i]);
#pragma unroll
    for (int j = 0; j < 3; j++) bb[j] = __ldg(&bp1[j]);
    float s0=0,s1=0,s2=0,q0=0,q1=0,q2=0;
    const int stride = gridDim.x * blockDim.x;
    for (int pr = blockIdx.x * blockDim.x + threadIdx.x; pr < PAIRS; pr += stride) {
        int n = pr >> 4;
        int idx = __ldg(&knn[pr]);
        float ax = p[idx*3+0]-p[n*3+0];
        float ay = p[idx*3+1]-p[n*3+1];
        float az = p[idx*3+2]-p[n*3+2];
        float u0 = fmaf(ax,w[0],fmaf(ay,w[3],fmaf(az,w[6],bb[0])));
        float u1 = fmaf(ax,w[1],fmaf(ay,w[4],fmaf(az,w[7],bb[1])));
        float u2 = fmaf(ax,w[2],fmaf(ay,w[5],fmaf(az,w[8],bb[2])));
        s0+=u0; s1+=u1; s2+=u2;
        q0=fmaf(u0,u0,q0); q1=fmaf(u1,u1,q1); q2=fmaf(u2,u2,q2);
    }
#pragma unroll
    for (int off = 16; off; off >>= 1) {
        s0 += __shfl_xor_sync(0xffffffffu, s0, off);
        s1 += __shfl_xor_sync(0xffffffffu, s1, off);
        s2 += __shfl_xor_sync(0xffffffffu, s2, off);
        q0 += __shfl_xor_sync(0xffffffffu, q0, off);
        q1 += __shfl_xor_sync(0xffffffffu, q1, off);
        q2 += __shfl_xor_sync(0xffffffffu, q2, off);
    }
    __shared__ float sm[6];
    if (threadIdx.x < 6) sm[threadIdx.x] = 0.f;
    __syncthreads();
    if ((threadIdx.x & 31) == 0) {
        atomicAdd(&sm[0], s0); atomicAdd(&sm[1], s1); atomicAdd(&sm[2], s2);
        atomicAdd(&sm[3], q0); atomicAdd(&sm[4], q1); atomicAdd(&sm[5], q2);
    }
    __syncthreads();
    if (threadIdx.x < 3) {
        atomicAdd(&st[128 + threadIdx.x], sm[threadIdx.x]);
        atomicAdd(&st[136 + threadIdx.x], sm[3 + threadIdx.x]);
    }
}

// pass A: channel stats of w = k[idx] - q[n] + pe  (64 ch over PAIRS). warp-per-pair.
__global__ void k_wstats(const float* __restrict__ p, const int* __restrict__ knn,
                         const float* __restrict__ Qm, const float* __restrict__ Km,
                         const float* __restrict__ Wp1, const float* __restrict__ bp1,
                         const float* __restrict__ pa, const float* __restrict__ pc,
                         const float* __restrict__ Wp2, const float* __restrict__ bp2,
                         float* __restrict__ st)
{
    const int lane = threadIdx.x & 31;
    const int c0 = lane, c1 = lane + 32;
    PeC pec; pec.load(Wp1, bp1, pa, pc);
    float P00=__ldg(&Wp2[c0]), P10=__ldg(&Wp2[64+c0]), P20=__ldg(&Wp2[128+c0]), B0=__ldg(&bp2[c0]);
    float P01=__ldg(&Wp2[c1]), P11=__ldg(&Wp2[64+c1]), P21=__ldg(&Wp2[128+c1]), B1=__ldg(&bp2[c1]);
    float s0=0,q0=0,s1=0,q1=0;
    const int warp = (blockIdx.x * blockDim.x + threadIdx.x) >> 5;
    const int nw = (gridDim.x * blockDim.x) >> 5;
    for (int pr = warp; pr < PAIRS; pr += nw) {
        int n = pr >> 4;
        int idx = __ldg(&knn[pr]);
        float ax = p[idx*3+0]-p[n*3+0];
        float ay = p[idx*3+1]-p[n*3+1];
        float az = p[idx*3+2]-p[n*3+2];
        float r0, r1, r2; pec.rel(ax, ay, az, r0, r1, r2);
        float pe0 = fmaf(r0,P00,fmaf(r1,P10,fmaf(r2,P20,B0)));
        float pe1 = fmaf(r0,P01,fmaf(r1,P11,fmaf(r2,P21,B1)));
        long ko = (long)idx * 64, qo = (long)n * 64;
        float wv0 = Km[ko+c0] - Qm[qo+c0] + pe0;
        float wv1 = Km[ko+c1] - Qm[qo+c1] + pe1;
        s0 += wv0; q0 = fmaf(wv0,wv0,q0);
        s1 += wv1; q1 = fmaf(wv1,wv1,q1);
    }
    __shared__ float sS[64], sQ[64];
    if (threadIdx.x < 64) { sS[threadIdx.x] = 0.f; sQ[threadIdx.x] = 0.f; }
    __syncthreads();
    atomicAdd(&sS[c0], s0); atomicAdd(&sQ[c0], q0);
    atomicAdd(&sS[c1], s1); atomicAdd(&sQ[c1], q1);
    __syncthreads();
    if (threadIdx.x < 64) {
        atomicAdd(&st[144 + threadIdx.x], sS[threadIdx.x]);
        atomicAdd(&st[208 + threadIdx.x], sQ[threadIdx.x]);
    }
}

// pass B: recompute w, bnw1+relu, @Ww1 + bw1 -> w1b (8 per pair). warp-per-pair.
__global__ void k_passB(const float* __restrict__ p, const int* __restrict__ knn,
                        const float* __restrict__ Qm, const float* __restrict__ Km,
                        const float* __restrict__ Wp1, const float* __restrict__ bp1,
                        const float* __restrict__ pa, const float* __restrict__ pc,
                        const float* __restrict__ Wp2, const float* __restrict__ bp2,
                        const float* __restrict__ w1a, const float* __restrict__ w1c,
                        const float* __restrict__ Ww1, const float* __restrict__ bw1,
                        float* __restrict__ w1out)
{
    __shared__ float sW[64][9];
    __shared__ float sBw[8];
    const int tid = threadIdx.x;
    for (int i = tid; i < 512; i += blockDim.x) sW[i >> 3][i & 7] = Ww1[i];
    if (tid < 8) sBw[tid] = bw1[tid];
    __syncthreads();
    const int lane = tid & 31;
    const int c0 = lane, c1 = lane + 32;
    PeC pec; pec.load(Wp1, bp1, pa, pc);
    float P00=__ldg(&Wp2[c0]), P10=__ldg(&Wp2[64+c0]), P20=__ldg(&Wp2[128+c0]), B0=__ldg(&bp2[c0]);
    float P01=__ldg(&Wp2[c1]), P11=__ldg(&Wp2[64+c1]), P21=__ldg(&Wp2[128+c1]), B1=__ldg(&bp2[c1]);
    float Aa0=__ldg(&w1a[c0]), Cc0=__ldg(&w1c[c0]);
    float Aa1=__ldg(&w1a[c1]), Cc1=__ldg(&w1c[c1]);
    const int warp = (blockIdx.x * blockDim.x + tid) >> 5;
    const int nw = (gridDim.x * blockDim.x) >> 5;
    for (int pr = warp; pr < PAIRS; pr += nw) {
        int n = pr >> 4;
        int idx = __ldg(&knn[pr]);
        float ax = p[idx*3+0]-p[n*3+0];
        float ay = p[idx*3+1]-p[n*3+1];
        float az = p[idx*3+2]-p[n*3+2];
        float r0, r1, r2; pec.rel(ax, ay, az, r0, r1, r2);
        float pe0 = fmaf(r0,P00,fmaf(r1,P10,fmaf(r2,P20,B0)));
        float pe1 = fmaf(r0,P01,fmaf(r1,P11,fmaf(r2,P21,B1)));
        long ko = (long)idx * 64, qo = (long)n * 64;
        float wv0 = Km[ko+c0] - Qm[qo+c0] + pe0;
        float wv1 = Km[ko+c1] - Qm[qo+c1] + pe1;
        float rw0 = fmaxf(fmaf(wv0, Aa0, Cc0), 0.f);
        float rw1 = fmaxf(fmaf(wv1, Aa1, Cc1), 0.f);
        float t[8];
#pragma unroll
        for (int o = 0; o < 8; o++) t[o] = fmaf(rw0, sW[c0][o], rw1 * sW[c1][o]);
#pragma unroll
        for (int off = 16; off; off >>= 1) {
#pragma unroll
            for (int o = 0; o < 8; o++) t[o] += __shfl_xor_sync(0xffffffffu, t[o], off);
        }
        if (lane == 0) {
            float* op = w1out + (long)pr * 8;
#pragma unroll
            for (int o = 0; o < 8; o++) op[o] = t[o] + sBw[o];
        }
    }
}

// pass C: bnw2+relu, @Ww2+bw2, softmax over NS, weighted (v_g+pe) aggregation.
// warp-per-point, blockDim must be 256.
__global__ void k_passC(const float* __restrict__ p, const int* __restrict__ knn,
                        const float* __restrict__ Vm, const float* __restrict__ w1in,
                        const float* __restrict__ Wp1, const float* __restrict__ bp1,
                        const float* __restrict__ pa, const float* __restrict__ pc,
                        const float* __restrict__ Wp2, const float* __restrict__ bp2,
                        const float* __restrict__ w2a, const float* __restrict__ w2c,
                        const float* __restrict__ Ww2, const float* __restrict__ bw2,
                        float* __restrict__ agg)
{
    __shared__ float sW2[8][8];
    __shared__ float sA[8], sC[8], sB[8];
    __shared__ float lsm[8][16][8];  // [warp][ns][o]
    const int tid = threadIdx.x;
    if (tid < 64) sW2[tid >> 3][tid & 7] = Ww2[tid];
    if (tid < 8) { sA[tid] = w2a[tid]; sC[tid] = w2c[tid]; sB[tid] = bw2[tid]; }
    __syncthreads();
    const int lane = tid & 31, wl = tid >> 5;
    const int c0 = lane, c1 = lane + 32;
    PeC pec; pec.load(Wp1, bp1, pa, pc);
    float P00=__ldg(&Wp2[c0]), P10=__ldg(&Wp2[64+c0]), P20=__ldg(&Wp2[128+c0]), B0=__ldg(&bp2[c0]);
    float P01=__ldg(&Wp2[c1]), P11=__ldg(&Wp2[64+c1]), P21=__ldg(&Wp2[128+c1]), B1=__ldg(&bp2[c1]);
    const int warp = (blockIdx.x * blockDim.x + tid) >> 5;
    const int nw = (gridDim.x * blockDim.x) >> 5;
    for (int n = warp; n < NPTS; n += nw) {
        // phase 1: logits per (ns, o)
        if (lane < 16) {
            const float4* wr = (const float4*)(w1in + ((long)n * 16 + lane) * 8);
            float4 lo = wr[0], hi = wr[1];
            float rv[8] = {lo.x, lo.y, lo.z, lo.w, hi.x, hi.y, hi.z, hi.w};
#pragma unroll
            for (int i = 0; i < 8; i++) rv[i] = fmaxf(fmaf(rv[i], sA[i], sC[i]), 0.f);
#pragma unroll
            for (int o = 0; o < 8; o++) {
                float lg = sB[o];
#pragma unroll
                for (int i = 0; i < 8; i++) lg = fmaf(rv[i], sW2[i][o], lg);
                lsm[wl][lane][o] = lg;
            }
        }
        __syncwarp();
        // phase 2: softmax over ns for each o
        if (lane < 8) {
            float m = -1e30f;
#pragma unroll
            for (int ns = 0; ns < 16; ns++) m = fmaxf(m, lsm[wl][ns][lane]);
            float ssum = 0.f;
#pragma unroll
            for (int ns = 0; ns < 16; ns++) {
                float e = __expf(lsm[wl][ns][lane] - m);
                lsm[wl][ns][lane] = e; ssum += e;
            }
            float inv = 1.f / ssum;
#pragma unroll
            for (int ns = 0; ns < 16; ns++) lsm[wl][ns][lane] *= inv;
        }
        __syncwarp();
        // phase 3: aggregation over neighbors
        float acc0 = 0.f, acc1 = 0.f;
        float px = p[n*3+0], py = p[n*3+1], pz = p[n*3+2];
        const int* kn = knn + n * 16;
        const int oo = lane & 7;
#pragma unroll 4
        for (int ns = 0; ns < 16; ns++) {
            int idx = __ldg(&kn[ns]);
            float ax = p[idx*3+0]-px, ay = p[idx*3+1]-py, az = p[idx*3+2]-pz;
            float r0, r1, r2; pec.rel(ax, ay, az, r0, r1, r2);
            float pe0 = fmaf(r0,P00,fmaf(r1,P10,fmaf(r2,P20,B0)));
            float pe1 = fmaf(r0,P01,fmaf(r1,P11,fmaf(r2,P21,B1)));
            float wt = lsm[wl][ns][oo];
            long vo = (long)idx * 64;
            acc0 = fmaf(Vm[vo+c0] + pe0, wt, acc0);
            acc1 = fmaf(Vm[vo+c1] + pe1, wt, acc1);
        }
        agg[(long)n*64 + c0] = acc0;
        agg[(long)n*64 + c1] = acc1;
        __syncwarp();  // protect lsm before next iteration overwrites
    }
}

// out = relu(bn3(t3) + x)
__global__ void k_final(const float* __restrict__ T3, const float* __restrict__ X,
                        const float* __restrict__ a, const float* __restrict__ c,
                        float* __restrict__ out)
{
    const int stride = gridDim.x * blockDim.x;
    for (int i = blockIdx.x * blockDim.x + threadIdx.x; i < NPTS * 16; i += stride) {
        int cb = (i * 4) & 63;
        float4 t = ((const float4*)T3)[i];
        float4 x4 = ((const float4*)X)[i];
        float4 r;
        r.x = fmaxf(fmaf(t.x, __ldg(&a[cb+0]), __ldg(&c[cb+0])) + x4.x, 0.f);
        r.y = fmaxf(fmaf(t.y, __ldg(&a[cb+1]), __ldg(&c[cb+1])) + x4.y, 0.f);
        r.z = fmaxf(fmaf(t.z, __ldg(&a[cb+2]), __ldg(&c[cb+2])) + x4.z, 0.f);
        r.w = fmaxf(fmaf(t.w, __ldg(&a[cb+3]), __ldg(&c[cb+3])) + x4.w, 0.f);
        ((float4*)out)[i] = r;
    }
}

// ---------------------------------------------------------------------------
extern "C" void kernel_launch(void* const* d_in, const int* in_sizes, int n_in,
                              void* d_out, int out_size)
{
    const float* p     = (const float*)d_in[0];
    const float* x     = (const float*)d_in[1];
    const int*   knn   = (const int*)  d_in[2];
    const float* W1    = (const float*)d_in[3];
    const float* bn1g  = (const float*)d_in[4];
    const float* bn1b  = (const float*)d_in[5];
    const float* Wq    = (const float*)d_in[6];
    const float* bq    = (const float*)d_in[7];
    const float* Wk    = (const float*)d_in[8];
    const float* bk    = (const float*)d_in[9];
    const float* Wv    = (const float*)d_in[10];
    const float* bv    = (const float*)d_in[11];
    const float* Wp1   = (const float*)d_in[12];
    const float* bp1   = (const float*)d_in[13];
    const float* bnpg  = (const float*)d_in[14];
    const float* bnpb  = (const float*)d_in[15];
    const float* Wp2   = (const float*)d_in[16];
    const float* bp2   = (const float*)d_in[17];
    const float* bnw1g = (const float*)d_in[18];
    const float* bnw1b = (const float*)d_in[19];
    const float* Ww1   = (const float*)d_in[20];
    const float* bw1   = (const float*)d_in[21];
    const float* bnw2g = (const float*)d_in[22];
    const float* bnw2b = (const float*)d_in[23];
    const float* Ww2   = (const float*)d_in[24];
    const float* bw2   = (const float*)d_in[25];
    const float* bn2g  = (const float*)d_in[26];
    const float* bn2b  = (const float*)d_in[27];
    const float* W3    = (const float*)d_in[28];
    const float* bn3g  = (const float*)d_in[29];
    const float* bn3b  = (const float*)d_in[30];
    float* out = (float*)d_out;

    float* scr = nullptr;
    cudaGetSymbolAddress((void**)&scr, g_scr);
    float* t1  = scr + OFF_T1;
    float* qb  = scr + OFF_Q;
    float* kb  = scr + OFF_K;
    float* vb  = scr + OFF_V;
    float* w1b = scr + OFF_W1B;
    float* agg = scr + OFF_AGG;
    float* t3  = scr + OFF_T3;
    float* st  = scr + OFF_STATS;
    float* pm  = scr + OFF_PRM;

    const float invN = 1.f / (float)NPTS;
    const float invP = 1.f / (float)PAIRS;

    k_zero<<<1, 544>>>(st);

    // linear1 + bn1
    k_gemm64<false><<<1250, 256>>>(x, W1, nullptr, nullptr, t1);
    k_colstats<64><<<1024, 256>>>(t1, NPTS, st + 0, st + 64);
    k_finalize<<<1, 64>>>(st + 0, st + 64, bn1g, bn1b, invN, pm + 0, pm + 64, 64);

    // q,k,v
    k_qkv<<<1250, 256>>>(t1, Wq, bq, Wk, bk, Wv, bv, pm + 0, pm + 64, qb, kb, vb);

    // bnp (positional mini-MLP first stage)
    k_pstats<<<1024, 256>>>(p, knn, Wp1, bp1, st);
    k_finalize<<<1, 64>>>(st + 128, st + 136, bnpg, bnpb, invP, pm + 128, pm + 136, 3);

    // bnw1 stats over w = k_g - q + pe
    k_wstats<<<1184, 256>>>(p, knn, qb, kb, Wp1, bp1, pm + 128, pm + 136, Wp2, bp2, st);
    k_finalize<<<1, 64>>>(st + 144, st + 208, bnw1g, bnw1b, invP, pm + 144, pm + 208, 64);

    // pass B: w1 = relu(bnw1(w)) @ Ww1 + bw1
    k_passB<<<1184, 256>>>(p, knn, qb, kb, Wp1, bp1, pm + 128, pm + 136, Wp2, bp2,
                           pm + 144, pm + 208, Ww1, bw1, w1b);
    k_colstats<8><<<2048, 256>>>(w1b, PAIRS, st + 272, st + 280);
    k_finalize<<<1, 64>>>(st + 272, st + 280, bnw2g, bnw2b, invP, pm + 272, pm + 280, 8);

    // pass C: logits -> softmax -> aggregation
    k_passC<<<1184, 256>>>(p, knn, vb, w1b, Wp1, bp1, pm + 128, pm + 136, Wp2, bp2,
                           pm + 272, pm + 280, Ww2, bw2, agg);
    k_colstats<64><<<1024, 256>>>(agg, NPTS, st + 288, st + 352);
    k_finalize<<<1, 64>>>(st + 288, st + 352, bn2g, bn2b, invN, pm + 288, pm + 352, 64);

    // linear3 + bn3
    k_gemm64<true><<<1250, 256>>>(agg, W3, pm + 288, pm + 352, t3);
    k_colstats<64><<<1024, 256>>>(t3, NPTS, st + 416, st + 480);
    k_finalize<<<1, 64>>>(st + 416, st + 480, bn3g, bn3b, invN, pm + 416, pm + 480, 64);

    // residual + relu
    k_final<<<640, 256>>>(t3, x, pm + 416, pm + 480, out);
}

// round 2
// speedup vs baseline: 1.3524x; 1.3524x over previous
#include <cuda_runtime.h>

#define NPTS 80000
#define NSAMP 16
#define PAIRS (NPTS*NSAMP)
#define EPSF 1e-5f
#define INV_N (1.0f/80000.0f)
#define INV_P (1.0f/1280000.0f)

// ---------------- scratch (device-global) ----------------
#define OFF_T1    0
#define OFF_Q     5120000
#define OFF_K     10240000
#define OFF_V     15360000
#define OFF_W1B   20480000
#define OFF_AGG   30720000
#define OFF_T3    35840000
#define OFF_STATS 40960000
__device__ float g_scr[40960640];

// stats sublayout (float offsets within st):
//  +0   bn1 sum(64)   | +64  bn1 sq(64)
//  +128 bnp sum(3)    | +136 bnp sq(3)
//  +144 bnw1 sum(64)  | +208 bnw1 sq(64)
//  +272 bnw2 sum(8)   | +280 bnw2 sq(8)
//  +288 bn2 sum(64)   | +352 bn2 sq(64)
//  +416 bn3 sum(64)   | +480 bn3 sq(64)

__global__ void k_zero(float* st) { int i = threadIdx.x; if (i < 544) st[i] = 0.f; }

// ---------------------------------------------------------------------------
// GEMM 64x64, optional input-BN (params computed inline from raw stats),
// fused output column stats (sum + sumsq) accumulated into st.
template<bool IN_BN>
__global__ void k_gemm64(const float* __restrict__ X, const float* __restrict__ W,
                         const float* __restrict__ st, const float* __restrict__ bg,
                         const float* __restrict__ bb, int inoff,
                         float* __restrict__ out, float* __restrict__ sto, int outoff)
{
    __shared__ float sX[64][65];
    __shared__ float sW[64][64];
    __shared__ float sA[64], sC[64];
    __shared__ float sS[64], sQ[64];
    const int tid = threadIdx.x;
    const long row0 = (long)blockIdx.x * 64;
    if (tid < 64) {
        sS[tid] = 0.f; sQ[tid] = 0.f;
        if (IN_BN) {
            float m = st[inoff + tid] * INV_N;
            float var = fmaf(-m, m, st[inoff + 64 + tid] * INV_N);
            float a = bg[tid] * rsqrtf(var + EPSF);
            sA[tid] = a; sC[tid] = fmaf(-m, a, bb[tid]);
        }
    }
    for (int i = tid; i < 4096; i += 256) sW[i >> 6][i & 63] = W[i];
    if (IN_BN) __syncthreads();
    for (int i = tid; i < 4096; i += 256) {
        int r = i >> 6, kk = i & 63;
        float val = X[(row0 + r) * 64 + kk];
        if (IN_BN) val = fmaxf(fmaf(val, sA[kk], sC[kk]), 0.f);
        sX[r][kk] = val;
    }
    __syncthreads();
    const int lane = tid & 31;
    const int r = tid & 63, c0 = (tid >> 6) << 4;
    float acc[16];
#pragma unroll
    for (int j = 0; j < 16; j++) acc[j] = 0.f;
#pragma unroll
    for (int kk = 0; kk < 64; kk++) {
        float xv = sX[r][kk];
#pragma unroll
        for (int j = 0; j < 16; j++) acc[j] = fmaf(xv, sW[kk][c0 + j], acc[j]);
    }
    float* op = out + (row0 + r) * 64 + c0;
#pragma unroll
    for (int j = 0; j < 16; j++) op[j] = acc[j];
    // fused column stats: shuffle-reduce 32 rows within warp, lane0 -> smem
#pragma unroll
    for (int j = 0; j < 16; j++) {
        float s = acc[j], q = acc[j] * acc[j];
#pragma unroll
        for (int off = 16; off; off >>= 1) {
            s += __shfl_xor_sync(0xffffffffu, s, off);
            q += __shfl_xor_sync(0xffffffffu, q, off);
        }
        if (lane == 0) { atomicAdd(&sS[c0 + j], s); atomicAdd(&sQ[c0 + j], q); }
    }
    __syncthreads();
    if (tid < 64) {
        atomicAdd(&sto[outoff + tid], sS[tid]);
        atomicAdd(&sto[outoff + 64 + tid], sQ[tid]);
    }
}

// q/k/v fused, bn1 params inline from raw stats
__global__ void k_qkv(const float* __restrict__ T1,
                      const float* __restrict__ Wq, const float* __restrict__ bq,
                      const float* __restrict__ Wk, const float* __restrict__ bk,
                      const float* __restrict__ Wv, const float* __restrict__ bv,
                      const float* __restrict__ st,
                      const float* __restrict__ g1, const float* __restrict__ b1,
                      float* __restrict__ oq, float* __restrict__ ok, float* __restrict__ ov)
{
    __shared__ float sX[64][65];
    __shared__ float sW[64][64];
    __shared__ float sA[64], sC[64];
    const int tid = threadIdx.x;
    const long row0 = (long)blockIdx.x * 64;
    if (tid < 64) {
        float m = st[tid] * INV_N;
        float var = fmaf(-m, m, st[64 + tid] * INV_N);
        float a = g1[tid] * rsqrtf(var + EPSF);
        sA[tid] = a; sC[tid] = fmaf(-m, a, b1[tid]);
    }
    __syncthreads();
    for (int i = tid; i < 4096; i += 256) {
        int r = i >> 6, kk = i & 63;
        sX[r][kk] = fmaxf(fmaf(T1[(row0 + r) * 64 + kk], sA[kk], sC[kk]), 0.f);
    }
    const int r = tid & 63, c0 = (tid >> 6) << 4;
    const float* Ws[3] = {Wq, Wk, Wv};
    const float* Bs[3] = {bq, bk, bv};
    float* Os[3] = {oq, ok, ov};
#pragma unroll 1
    for (int m = 0; m < 3; m++) {
        __syncthreads();
        for (int i = tid; i < 4096; i += 256) sW[i >> 6][i & 63] = Ws[m][i];
        __syncthreads();
        float acc[16];
#pragma unroll
        for (int j = 0; j < 16; j++) acc[j] = __ldg(&Bs[m][c0 + j]);
#pragma unroll
        for (int kk = 0; kk < 64; kk++) {
            float xv = sX[r][kk];
#pragma unroll
            for (int j = 0; j < 16; j++) acc[j] = fmaf(xv, sW[kk][c0 + j], acc[j]);
        }
        float* op = Os[m] + (row0 + r) * 64 + c0;
#pragma unroll
        for (int j = 0; j < 16; j++) op[j] = acc[j];
    }
}

// ---------------------------------------------------------------------------
// positional mini-MLP helper: constants + relu'd first stage
struct PeC {
    float w0,w1,w2,w3,w4,w5,w6,w7,w8,b0,b1,b2,A0,A1,A2,C0,C1,C2;
    __device__ __forceinline__ void load(const float* Wp1, const float* bp1,
                                         const float* st,
                                         const float* bnpg, const float* bnpb) {
        w0=__ldg(&Wp1[0]); w1=__ldg(&Wp1[1]); w2=__ldg(&Wp1[2]);
        w3=__ldg(&Wp1[3]); w4=__ldg(&Wp1[4]); w5=__ldg(&Wp1[5]);
        w6=__ldg(&Wp1[6]); w7=__ldg(&Wp1[7]); w8=__ldg(&Wp1[8]);
        b0=__ldg(&bp1[0]); b1=__ldg(&bp1[1]); b2=__ldg(&bp1[2]);
#pragma unroll
        for (int j = 0; j < 3; j++) {
            float m = __ldg(&st[128 + j]) * INV_P;
            float var = fmaf(-m, m, __ldg(&st[136 + j]) * INV_P);
            float a = __ldg(&bnpg[j]) * rsqrtf(var + EPSF);
            float c = fmaf(-m, a, __ldg(&bnpb[j]));
            if (j == 0) { A0 = a; C0 = c; }
            else if (j == 1) { A1 = a; C1 = c; }
            else { A2 = a; C2 = c; }
        }
    }
    __device__ __forceinline__ void rel(float ax, float ay, float az,
                                        float& r0, float& r1, float& r2) const {
        r0 = fmaxf(fmaf(fmaf(ax,w0,fmaf(ay,w3,fmaf(az,w6,b0))), A0, C0), 0.f);
        r1 = fmaxf(fmaf(fmaf(ax,w1,fmaf(ay,w4,fmaf(az,w7,b1))), A1, C1), 0.f);
        r2 = fmaxf(fmaf(fmaf(ax,w2,fmaf(ay,w5,fmaf(az,w8,b2))), A2, C2), 0.f);
    }
};

// stats for bn of (p_r @ Wp1 + bp1): 3 channels over PAIRS (thread-per-pair)
__global__ void k_pstats(const float* __restrict__ p, const int* __restrict__ knn,
                         const float* __restrict__ Wp1, const float* __restrict__ bp1,
                         float* __restrict__ st)
{
    float w[9], bb[3];
#pragma unroll
    for (int i = 0; i < 9; i++) w[i] = __ldg(&Wp1[i]);
#pragma unroll
    for (int j = 0; j < 3; j++) bb[j] = __ldg(&bp1[j]);
    float s0=0,s1=0,s2=0,q0=0,q1=0,q2=0;
    const int stride = gridDim.x * blockDim.x;
    for (int pr = blockIdx.x * blockDim.x + threadIdx.x; pr < PAIRS; pr += stride) {
        int n = pr >> 4;
        int idx = __ldg(&knn[pr]);
        float ax = p[idx*3+0]-p[n*3+0];
        float ay = p[idx*3+1]-p[n*3+1];
        float az = p[idx*3+2]-p[n*3+2];
        float u0 = fmaf(ax,w[0],fmaf(ay,w[3],fmaf(az,w[6],bb[0])));
        float u1 = fmaf(ax,w[1],fmaf(ay,w[4],fmaf(az,w[7],bb[1])));
        float u2 = fmaf(ax,w[2],fmaf(ay,w[5],fmaf(az,w[8],bb[2])));
        s0+=u0; s1+=u1; s2+=u2;
        q0=fmaf(u0,u0,q0); q1=fmaf(u1,u1,q1); q2=fmaf(u2,u2,q2);
    }
#pragma unroll
    for (int off = 16; off; off >>= 1) {
        s0 += __shfl_xor_sync(0xffffffffu, s0, off);
        s1 += __shfl_xor_sync(0xffffffffu, s1, off);
        s2 += __shfl_xor_sync(0xffffffffu, s2, off);
        q0 += __shfl_xor_sync(0xffffffffu, q0, off);
        q1 += __shfl_xor_sync(0xffffffffu, q1, off);
        q2 += __shfl_xor_sync(0xffffffffu, q2, off);
    }
    __shared__ float sm[6];
    if (threadIdx.x < 6) sm[threadIdx.x] = 0.f;
    __syncthreads();
    if ((threadIdx.x & 31) == 0) {
        atomicAdd(&sm[0], s0); atomicAdd(&sm[1], s1); atomicAdd(&sm[2], s2);
        atomicAdd(&sm[3], q0); atomicAdd(&sm[4], q1); atomicAdd(&sm[5], q2);
    }
    __syncthreads();
    if (threadIdx.x < 3) {
        atomicAdd(&st[128 + threadIdx.x], sm[threadIdx.x]);
        atomicAdd(&st[136 + threadIdx.x], sm[3 + threadIdx.x]);
    }
}

// ---------------------------------------------------------------------------
// pass A: channel stats of w = k_g - q + pe, warp-per-POINT (q/p/knn amortized)
__global__ void k_wstats(const float* __restrict__ p, const int* __restrict__ knn,
                         const float* __restrict__ Qm, const float* __restrict__ Km,
                         const float* __restrict__ Wp1, const float* __restrict__ bp1,
                         const float* __restrict__ bnpg, const float* __restrict__ bnpb,
                         const float* __restrict__ Wp2, const float* __restrict__ bp2,
                         float* __restrict__ st)
{
    const int tid = threadIdx.x, lane = tid & 31;
    const int c0 = lane, c1 = lane + 32;
    PeC pec; pec.load(Wp1, bp1, st, bnpg, bnpb);
    float P00=__ldg(&Wp2[c0]), P10=__ldg(&Wp2[64+c0]), P20=__ldg(&Wp2[128+c0]), B0=__ldg(&bp2[c0]);
    float P01=__ldg(&Wp2[c1]), P11=__ldg(&Wp2[64+c1]), P21=__ldg(&Wp2[128+c1]), B1=__ldg(&bp2[c1]);
    float s0=0,q0=0,s1=0,q1=0;
    const int warp = (blockIdx.x * blockDim.x + tid) >> 5;
    const int nw = (gridDim.x * blockDim.x) >> 5;
    for (int n = warp; n < NPTS; n += nw) {
        float qv0 = Qm[(long)n*64 + c0], qv1 = Qm[(long)n*64 + c1];
        float px = __ldg(&p[n*3+0]), py = __ldg(&p[n*3+1]), pz = __ldg(&p[n*3+2]);
        int mk = (lane < 16) ? __ldg(&knn[n*16 + lane]) : 0;
#pragma unroll 4
        for (int ns = 0; ns < 16; ns++) {
            int idx = __shfl_sync(0xffffffffu, mk, ns);
            float ax = __ldg(&p[idx*3+0])-px, ay = __ldg(&p[idx*3+1])-py, az = __ldg(&p[idx*3+2])-pz;
            float r0, r1, r2; pec.rel(ax, ay, az, r0, r1, r2);
            float pe0 = fmaf(r0,P00,fmaf(r1,P10,fmaf(r2,P20,B0)));
            float pe1 = fmaf(r0,P01,fmaf(r1,P11,fmaf(r2,P21,B1)));
            long ko = (long)idx * 64;
            float wv0 = Km[ko+c0] - qv0 + pe0;
            float wv1 = Km[ko+c1] - qv1 + pe1;
            s0 += wv0; q0 = fmaf(wv0,wv0,q0);
            s1 += wv1; q1 = fmaf(wv1,wv1,q1);
        }
    }
    __shared__ float sS[64], sQ[64];
    if (tid < 64) { sS[tid] = 0.f; sQ[tid] = 0.f; }
    __syncthreads();
    atomicAdd(&sS[c0], s0); atomicAdd(&sQ[c0], q0);
    atomicAdd(&sS[c1], s1); atomicAdd(&sQ[c1], q1);
    __syncthreads();
    if (tid < 64) {
        atomicAdd(&st[144 + tid], sS[tid]);
        atomicAdd(&st[208 + tid], sQ[tid]);
    }
}

// ---------------------------------------------------------------------------
// pass B: recompute w, bnw1+relu -> smem stage -> GEMV 64->8 (no shuffles),
// coalesced float4 stores, fused bnw2 column stats. Warp-per-point.
__global__ void __launch_bounds__(256) k_passB(
        const float* __restrict__ p, const int* __restrict__ knn,
        const float* __restrict__ Qm, const float* __restrict__ Km,
        const float* __restrict__ Wp1, const float* __restrict__ bp1,
        const float* __restrict__ bnpg, const float* __restrict__ bnpb,
        const float* __restrict__ Wp2, const float* __restrict__ bp2,
        const float* __restrict__ g1, const float* __restrict__ b1,
        const float* __restrict__ Ww1, const float* __restrict__ bw1,
        float* __restrict__ w1out, float* __restrict__ st)
{
    __shared__ float sWw1[64][8];
    __shared__ float sBw[8];
    __shared__ float sWm[8][16][65];
    __shared__ float sS8[8], sQ8[8];
    const int tid = threadIdx.x, lane = tid & 31, wl = tid >> 5;
    for (int i = tid; i < 512; i += 256) sWw1[i >> 3][i & 7] = Ww1[i];
    if (tid < 8) { sBw[tid] = bw1[tid]; sS8[tid] = 0.f; sQ8[tid] = 0.f; }
    __syncthreads();
    const int c0 = lane, c1 = lane + 32;
    PeC pec; pec.load(Wp1, bp1, st, bnpg, bnpb);
    float P00=__ldg(&Wp2[c0]), P10=__ldg(&Wp2[64+c0]), P20=__ldg(&Wp2[128+c0]), B0=__ldg(&bp2[c0]);
    float P01=__ldg(&Wp2[c1]), P11=__ldg(&Wp2[64+c1]), P21=__ldg(&Wp2[128+c1]), B1=__ldg(&bp2[c1]);
    // bnw1 params for this lane's two channels (from raw sums)
    float m0 = __ldg(&st[144+c0]) * INV_P;
    float Aa0 = __ldg(&g1[c0]) * rsqrtf(fmaf(-m0, m0, __ldg(&st[208+c0]) * INV_P) + EPSF);
    float Cc0 = fmaf(-m0, Aa0, __ldg(&b1[c0]));
    float m1 = __ldg(&st[144+c1]) * INV_P;
    float Aa1 = __ldg(&g1[c1]) * rsqrtf(fmaf(-m1, m1, __ldg(&st[208+c1]) * INV_P) + EPSF);
    float Cc1 = fmaf(-m1, Aa1, __ldg(&b1[c1]));

    const int pair = lane >> 1, ob = (lane & 1) << 2;
    float sAcc[4] = {0,0,0,0}, qAcc[4] = {0,0,0,0};
    const int warp = (blockIdx.x * blockDim.x + tid) >> 5;
    const int nw = (gridDim.x * blockDim.x) >> 5;
    for (int n = warp; n < NPTS; n += nw) {
        float qv0 = Qm[(long)n*64 + c0], qv1 = Qm[(long)n*64 + c1];
        float px = __ldg(&p[n*3+0]), py = __ldg(&p[n*3+1]), pz = __ldg(&p[n*3+2]);
        int mk = (lane < 16) ? __ldg(&knn[n*16 + lane]) : 0;
#pragma unroll 4
        for (int ns = 0; ns < 16; ns++) {
            int idx = __shfl_sync(0xffffffffu, mk, ns);
            float ax = __ldg(&p[idx*3+0])-px, ay = __ldg(&p[idx*3+1])-py, az = __ldg(&p[idx*3+2])-pz;
            float r0, r1, r2; pec.rel(ax, ay, az, r0, r1, r2);
            float pe0 = fmaf(r0,P00,fmaf(r1,P10,fmaf(r2,P20,B0)));
            float pe1 = fmaf(r0,P01,fmaf(r1,P11,fmaf(r2,P21,B1)));
            long ko = (long)idx * 64;
            float wv0 = Km[ko+c0] - qv0 + pe0;
            float wv1 = Km[ko+c1] - qv1 + pe1;
            sWm[wl][ns][c0] = fmaxf(fmaf(wv0, Aa0, Cc0), 0.f);
            sWm[wl][ns][c1] = fmaxf(fmaf(wv1, Aa1, Cc1), 0.f);
        }
        __syncwarp();
        // GEMV: lane computes 4 outputs for its pair
        float a0=0.f, a1=0.f, a2=0.f, a3=0.f;
#pragma unroll
        for (int ch = 0; ch < 64; ch++) {
            float wv = sWm[wl][pair][ch];
            a0 = fmaf(wv, sWw1[ch][ob+0], a0);
            a1 = fmaf(wv, sWw1[ch][ob+1], a1);
            a2 = fmaf(wv, sWw1[ch][ob+2], a2);
            a3 = fmaf(wv, sWw1[ch][ob+3], a3);
        }
        float4 t;
        t.x = a0 + sBw[ob+0]; t.y = a1 + sBw[ob+1];
        t.z = a2 + sBw[ob+2]; t.w = a3 + sBw[ob+3];
        ((float4*)(w1out + (long)n*128))[lane] = t;
        sAcc[0]+=t.x; qAcc[0]=fmaf(t.x,t.x,qAcc[0]);
        sAcc[1]+=t.y; qAcc[1]=fmaf(t.y,t.y,qAcc[1]);
        sAcc[2]+=t.z; qAcc[2]=fmaf(t.z,t.z,qAcc[2]);
        sAcc[3]+=t.w; qAcc[3]=fmaf(t.w,t.w,qAcc[3]);
        __syncwarp();
    }
    // reduce stats across lanes with same (lane&1)
#pragma unroll
    for (int off = 16; off >= 2; off >>= 1) {
#pragma unroll
        for (int j = 0; j < 4; j++) {
            sAcc[j] += __shfl_xor_sync(0xffffffffu, sAcc[j], off);
            qAcc[j] += __shfl_xor_sync(0xffffffffu, qAcc[j], off);
        }
    }
    if (lane < 2) {
#pragma unroll
        for (int j = 0; j < 4; j++) {
            atomicAdd(&sS8[ob + j], sAcc[j]);
            atomicAdd(&sQ8[ob + j], qAcc[j]);
        }
    }
    __syncthreads();
    if (tid < 8) {
        atomicAdd(&st[272 + tid], sS8[tid]);
        atomicAdd(&st[280 + tid], sQ8[tid]);
    }
}

// ---------------------------------------------------------------------------
// pass C: bnw2+relu -> logits -> softmax over NS -> weighted (v_g+pe) agg,
// fused bn2 column stats. Warp-per-point.
__global__ void __launch_bounds__(256) k_passC(
        const float* __restrict__ p, const int* __restrict__ knn,
        const float* __restrict__ Vm, const float* __restrict__ w1in,
        const float* __restrict__ Wp1, const float* __restrict__ bp1,
        const float* __restrict__ bnpg, const float* __restrict__ bnpb,
        const float* __restrict__ Wp2, const float* __restrict__ bp2,
        const float* __restrict__ g2, const float* __restrict__ b2,
        const float* __restrict__ Ww2, const float* __restrict__ bw2,
        float* __restrict__ agg, float* __restrict__ st)
{
    __shared__ float sW2[8][8];
    __shared__ float sA8[8], sC8[8], sB8[8];
    __shared__ float wsm[8][8][16];   // [warp][o][ns]
    __shared__ float sS[64], sQ[64];
    const int tid = threadIdx.x, lane = tid & 31, wl = tid >> 5;
    if (tid < 64) { sW2[tid >> 3][tid & 7] = Ww2[tid]; sS[tid] = 0.f; sQ[tid] = 0.f; }
    if (tid < 8) {
        float m = st[272 + tid] * INV_P;
        float var = fmaf(-m, m, st[280 + tid] * INV_P);
        float a = g2[tid] * rsqrtf(var + EPSF);
        sA8[tid] = a; sC8[tid] = fmaf(-m, a, b2[tid]);
        sB8[tid] = bw2[tid];
    }
    __syncthreads();
    const int c0 = lane, c1 = lane + 32;
    PeC pec; pec.load(Wp1, bp1, st, bnpg, bnpb);
    float P00=__ldg(&Wp2[c0]), P10=__ldg(&Wp2[64+c0]), P20=__ldg(&Wp2[128+c0]), B0=__ldg(&bp2[c0]);
    float P01=__ldg(&Wp2[c1]), P11=__ldg(&Wp2[64+c1]), P21=__ldg(&Wp2[128+c1]), B1=__ldg(&bp2[c1]);
    const int pair = lane >> 1, ob = (lane & 1) << 2;
    const int oo = lane & 7;
    float s0=0,q0=0,s1=0,q1=0;
    const int warp = (blockIdx.x * blockDim.x + tid) >> 5;
    const int nw = (gridDim.x * blockDim.x) >> 5;
    for (int n = warp; n < NPTS; n += nw) {
        // phase 1: logits (each lane: 4 outputs for its pair)
        {
            const float4* wp = (const float4*)(w1in + (long)n*128 + pair*8);
            float4 lo = wp[0], hi = wp[1];
            float rv[8] = {lo.x, lo.y, lo.z, lo.w, hi.x, hi.y, hi.z, hi.w};
#pragma unroll
            for (int i = 0; i < 8; i++) rv[i] = fmaxf(fmaf(rv[i], sA8[i], sC8[i]), 0.f);
#pragma unroll
            for (int j = 0; j < 4; j++) {
                int o = ob + j;
                float lg = sB8[o];
#pragma unroll
                for (int i = 0; i < 8; i++) lg = fmaf(rv[i], sW2[i][o], lg);
                wsm[wl][o][pair] = lg;
            }
        }
        __syncwarp();
        // phase 2: softmax over ns (8 lanes, one per output channel)
        if (lane < 8) {
            float* row = wsm[wl][lane];
            float m = -1e30f;
#pragma unroll
            for (int ns = 0; ns < 16; ns++) m = fmaxf(m, row[ns]);
            float ssum = 0.f;
#pragma unroll
            for (int ns = 0; ns < 16; ns++) { float e = __expf(row[ns] - m); row[ns] = e; ssum += e; }
            float inv = 1.f / ssum;
#pragma unroll
            for (int ns = 0; ns < 16; ns++) row[ns] *= inv;
        }
        __syncwarp();
        // phase 3: preload weights, aggregate over neighbors
        float wts[16];
        {
            const float4* wr = (const float4*)wsm[wl][oo];
#pragma unroll
            for (int t4 = 0; t4 < 4; t4++) {
                float4 v = wr[t4];
                wts[t4*4+0]=v.x; wts[t4*4+1]=v.y; wts[t4*4+2]=v.z; wts[t4*4+3]=v.w;
            }
        }
        float acc0 = 0.f, acc1 = 0.f;
        float px = __ldg(&p[n*3+0]), py = __ldg(&p[n*3+1]), pz = __ldg(&p[n*3+2]);
        int mk = (lane < 16) ? __ldg(&knn[n*16 + lane]) : 0;
#pragma unroll 4
        for (int ns = 0; ns < 16; ns++) {
            int idx = __shfl_sync(0xffffffffu, mk, ns);
            float ax = __ldg(&p[idx*3+0])-px, ay = __ldg(&p[idx*3+1])-py, az = __ldg(&p[idx*3+2])-pz;
            float r0, r1, r2; pec.rel(ax, ay, az, r0, r1, r2);
            float pe0 = fmaf(r0,P00,fmaf(r1,P10,fmaf(r2,P20,B0)));
            float pe1 = fmaf(r0,P01,fmaf(r1,P11,fmaf(r2,P21,B1)));
            long vo = (long)idx * 64;
            acc0 = fmaf(Vm[vo+c0] + pe0, wts[ns], acc0);
            acc1 = fmaf(Vm[vo+c1] + pe1, wts[ns], acc1);
        }
        agg[(long)n*64 + c0] = acc0;
        agg[(long)n*64 + c1] = acc1;
        s0 += acc0; q0 = fmaf(acc0,acc0,q0);
        s1 += acc1; q1 = fmaf(acc1,acc1,q1);
        __syncwarp();
    }
    atomicAdd(&sS[c0], s0); atomicAdd(&sQ[c0], q0);
    atomicAdd(&sS[c1], s1); atomicAdd(&sQ[c1], q1);
    __syncthreads();
    if (tid < 64) {
        atomicAdd(&st[288 + tid], sS[tid]);
        atomicAdd(&st[352 + tid], sQ[tid]);
    }
}

// out = relu(bn3(t3) + x), bn3 params inline
__global__ void k_final(const float* __restrict__ T3, const float* __restrict__ X,
                        const float* __restrict__ st,
                        const float* __restrict__ g3, const float* __restrict__ b3,
                        float* __restrict__ out)
{
    __shared__ float sA[64], sC[64];
    const int tid = threadIdx.x;
    if (tid < 64) {
        float m = st[416 + tid] * INV_N;
        float var = fmaf(-m, m, st[480 + tid] * INV_N);
        float a = g3[tid] * rsqrtf(var + EPSF);
        sA[tid] = a; sC[tid] = fmaf(-m, a, b3[tid]);
    }
    __syncthreads();
    const int stride = gridDim.x * blockDim.x;
    for (int i = blockIdx.x * blockDim.x + tid; i < NPTS * 16; i += stride) {
        int cb = (i * 4) & 63;
        float4 t = ((const float4*)T3)[i];
        float4 x4 = ((const float4*)X)[i];
        float4 r;
        r.x = fmaxf(fmaf(t.x, sA[cb+0], sC[cb+0]) + x4.x, 0.f);
        r.y = fmaxf(fmaf(t.y, sA[cb+1], sC[cb+1]) + x4.y, 0.f);
        r.z = fmaxf(fmaf(t.z, sA[cb+2], sC[cb+2]) + x4.z, 0.f);
        r.w = fmaxf(fmaf(t.w, sA[cb+3], sC[cb+3]) + x4.w, 0.f);
        ((float4*)out)[i] = r;
    }
}

// ---------------------------------------------------------------------------
extern "C" void kernel_launch(void* const* d_in, const int* in_sizes, int n_in,
                              void* d_out, int out_size)
{
    const float* p     = (const float*)d_in[0];
    const float* x     = (const float*)d_in[1];
    const int*   knn   = (const int*)  d_in[2];
    const float* W1    = (const float*)d_in[3];
    const float* bn1g  = (const float*)d_in[4];
    const float* bn1b  = (const float*)d_in[5];
    const float* Wq    = (const float*)d_in[6];
    const float* bq    = (const float*)d_in[7];
    const float* Wk    = (const float*)d_in[8];
    const float* bk    = (const float*)d_in[9];
    const float* Wv    = (const float*)d_in[10];
    const float* bv    = (const float*)d_in[11];
    const float* Wp1   = (const float*)d_in[12];
    const float* bp1   = (const float*)d_in[13];
    const float* bnpg  = (const float*)d_in[14];
    const float* bnpb  = (const float*)d_in[15];
    const float* Wp2   = (const float*)d_in[16];
    const float* bp2   = (const float*)d_in[17];
    const float* bnw1g = (const float*)d_in[18];
    const float* bnw1b = (const float*)d_in[19];
    const float* Ww1   = (const float*)d_in[20];
    const float* bw1   = (const float*)d_in[21];
    const float* bnw2g = (const float*)d_in[22];
    const float* bnw2b = (const float*)d_in[23];
    const float* Ww2   = (const float*)d_in[24];
    const float* bw2   = (const float*)d_in[25];
    const float* bn2g  = (const float*)d_in[26];
    const float* bn2b  = (const float*)d_in[27];
    const float* W3    = (const float*)d_in[28];
    const float* bn3g  = (const float*)d_in[29];
    const float* bn3b  = (const float*)d_in[30];
    float* out = (float*)d_out;

    float* scr = nullptr;
    cudaGetSymbolAddress((void**)&scr, g_scr);
    float* t1  = scr + OFF_T1;
    float* qb  = scr + OFF_Q;
    float* kb  = scr + OFF_K;
    float* vb  = scr + OFF_V;
    float* w1b = scr + OFF_W1B;
    float* agg = scr + OFF_AGG;
    float* t3  = scr + OFF_T3;
    float* st  = scr + OFF_STATS;

    k_zero<<<1, 544>>>(st);

    // linear1 (+ fused bn1 stats)
    k_gemm64<false><<<1250, 256>>>(x, W1, nullptr, nullptr, nullptr, 0, t1, st, 0);

    // q,k,v (bn1 applied inline)
    k_qkv<<<1250, 256>>>(t1, Wq, bq, Wk, bk, Wv, bv, st, bn1g, bn1b, qb, kb, vb);

    // bnp stats
    k_pstats<<<1024, 256>>>(p, knn, Wp1, bp1, st);

    // bnw1 stats over w = k_g - q + pe
    k_wstats<<<1184, 256>>>(p, knn, qb, kb, Wp1, bp1, bnpg, bnpb, Wp2, bp2, st);

    // pass B: w1 = relu(bnw1(w)) @ Ww1 + bw1 (+ fused bnw2 stats)
    k_passB<<<888, 256>>>(p, knn, qb, kb, Wp1, bp1, bnpg, bnpb, Wp2, bp2,
                          bnw1g, bnw1b, Ww1, bw1, w1b, st);

    // pass C: logits -> softmax -> aggregation (+ fused bn2 stats)
    k_passC<<<1184, 256>>>(p, knn, vb, w1b, Wp1, bp1, bnpg, bnpb, Wp2, bp2,
                           bnw2g, bnw2b, Ww2, bw2, agg, st);

    // linear3 (bn2 inline, + fused bn3 stats)
    k_gemm64<true><<<1250, 256>>>(agg, W3, st, bn2g, bn2b, 288, t3, st, 416);

    // residual + relu (bn3 inline)
    k_final<<<640, 256>>>(t3, x, st, bn3g, bn3b, out);
}

// round 3
// speedup vs baseline: 1.7376x; 1.2848x over previous
#include <cuda_runtime.h>

#define NPTS 80000
#define NSAMP 16
#define PAIRS (NPTS*NSAMP)
#define EPSF 1e-5f
#define INV_N (1.0f/80000.0f)
#define INV_P (1.0f/1280000.0f)
#define GEMM_BLOCKS 1250
#define PST_BLOCKS  1024

// ---------------- scratch (device-global) ----------------
#define OFF_T1    0
#define OFF_Q     5120000
#define OFF_K     10240000
#define OFF_V     15360000
#define OFF_W1B   20480000
#define OFF_AGG   30720000
#define OFF_T3    35840000
#define OFF_U     40960000           /* float4 per pair: u0,u1,u2,pad */
#define OFF_STATS 46080000
__device__ float g_scr[46080640];

// stats sublayout:
//  +0   bn1 sum(64)   | +64  bn1 sq(64)
//  +128 bnp sum(3)    | +136 bnp sq(3)
//  +144 bnw1 sum(64)  | +208 bnw1 sq(64)
//  +272 bnw2 sum(8)   | +280 bnw2 sq(8)
//  +288 bn2 sum(64)   | +352 bn2 sq(64)
//  +416 bn3 sum(64)   | +480 bn3 sq(64)

__global__ void k_zero(float* st) { int i = threadIdx.x; if (i < 544) st[i] = 0.f; }

// ---------------------------------------------------------------------------
// heterogeneous: blocks [0,1250) = gemm1 (t1 = x@W1, fused bn1 stats);
//                blocks [1250,2274) = pstats (+ u store)
__global__ void __launch_bounds__(256) k_g1p(
        const float* __restrict__ X, const float* __restrict__ W,
        float* __restrict__ out, float* __restrict__ st,
        const float* __restrict__ p, const int* __restrict__ knn,
        const float* __restrict__ Wp1, const float* __restrict__ bp1,
        float4* __restrict__ U)
{
    const int tid = threadIdx.x;
    if (blockIdx.x < GEMM_BLOCKS) {
        __shared__ float sX[64][65];
        __shared__ float sW[64][64];
        __shared__ float sS[64], sQ[64];
        const long row0 = (long)blockIdx.x * 64;
        if (tid < 64) { sS[tid] = 0.f; sQ[tid] = 0.f; }
        for (int i = tid; i < 4096; i += 256) sW[i >> 6][i & 63] = W[i];
        for (int i = tid; i < 4096; i += 256) {
            int r = i >> 6, kk = i & 63;
            sX[r][kk] = X[(row0 + r) * 64 + kk];
        }
        __syncthreads();
        const int lane = tid & 31;
        const int r = tid & 63, c0 = (tid >> 6) << 4;
        float acc[16];
#pragma unroll
        for (int j = 0; j < 16; j++) acc[j] = 0.f;
#pragma unroll
        for (int kk = 0; kk < 64; kk++) {
            float xv = sX[r][kk];
#pragma unroll
            for (int j = 0; j < 16; j++) acc[j] = fmaf(xv, sW[kk][c0 + j], acc[j]);
        }
        float* op = out + (row0 + r) * 64 + c0;
#pragma unroll
        for (int j = 0; j < 16; j++) op[j] = acc[j];
#pragma unroll
        for (int j = 0; j < 16; j++) {
            float s = acc[j], q = acc[j] * acc[j];
#pragma unroll
            for (int off = 16; off; off >>= 1) {
                s += __shfl_xor_sync(0xffffffffu, s, off);
                q += __shfl_xor_sync(0xffffffffu, q, off);
            }
            if (lane == 0) { atomicAdd(&sS[c0 + j], s); atomicAdd(&sQ[c0 + j], q); }
        }
        __syncthreads();
        if (tid < 64) {
            atomicAdd(&st[tid], sS[tid]);
            atomicAdd(&st[64 + tid], sQ[tid]);
        }
    } else {
        // pstats path: thread-per-pair, store u, accumulate 3-ch stats
        float w[9], bb[3];
#pragma unroll
        for (int i = 0; i < 9; i++) w[i] = __ldg(&Wp1[i]);
#pragma unroll
        for (int j = 0; j < 3; j++) bb[j] = __ldg(&bp1[j]);
        float s0=0,s1=0,s2=0,q0=0,q1=0,q2=0;
        const int bid = blockIdx.x - GEMM_BLOCKS;
        const int stride = PST_BLOCKS * 256;
        for (int pr = bid * 256 + tid; pr < PAIRS; pr += stride) {
            int n = pr >> 4;
            int idx = __ldg(&knn[pr]);
            float ax = p[idx*3+0]-p[n*3+0];
            float ay = p[idx*3+1]-p[n*3+1];
            float az = p[idx*3+2]-p[n*3+2];
            float u0 = fmaf(ax,w[0],fmaf(ay,w[3],fmaf(az,w[6],bb[0])));
            float u1 = fmaf(ax,w[1],fmaf(ay,w[4],fmaf(az,w[7],bb[1])));
            float u2 = fmaf(ax,w[2],fmaf(ay,w[5],fmaf(az,w[8],bb[2])));
            U[pr] = make_float4(u0, u1, u2, 0.f);
            s0+=u0; s1+=u1; s2+=u2;
            q0=fmaf(u0,u0,q0); q1=fmaf(u1,u1,q1); q2=fmaf(u2,u2,q2);
        }
#pragma unroll
        for (int off = 16; off; off >>= 1) {
            s0 += __shfl_xor_sync(0xffffffffu, s0, off);
            s1 += __shfl_xor_sync(0xffffffffu, s1, off);
            s2 += __shfl_xor_sync(0xffffffffu, s2, off);
            q0 += __shfl_xor_sync(0xffffffffu, q0, off);
            q1 += __shfl_xor_sync(0xffffffffu, q1, off);
            q2 += __shfl_xor_sync(0xffffffffu, q2, off);
        }
        __shared__ float sm[6];
        if (tid < 6) sm[tid] = 0.f;
        __syncthreads();
        if ((tid & 31) == 0) {
            atomicAdd(&sm[0], s0); atomicAdd(&sm[1], s1); atomicAdd(&sm[2], s2);
            atomicAdd(&sm[3], q0); atomicAdd(&sm[4], q1); atomicAdd(&sm[5], q2);
        }
        __syncthreads();
        if (tid < 3) {
            atomicAdd(&st[128 + tid], sm[tid]);
            atomicAdd(&st[136 + tid], sm[3 + tid]);
        }
    }
}

// q/k/v fused, bn1 params inline from raw stats
__global__ void k_qkv(const float* __restrict__ T1,
                      const float* __restrict__ Wq, const float* __restrict__ bq,
                      const float* __restrict__ Wk, const float* __restrict__ bk,
                      const float* __restrict__ Wv, const float* __restrict__ bv,
                      const float* __restrict__ st,
                      const float* __restrict__ g1, const float* __restrict__ b1,
                      float* __restrict__ oq, float* __restrict__ ok, float* __restrict__ ov)
{
    __shared__ float sX[64][65];
    __shared__ float sW[64][64];
    __shared__ float sA[64], sC[64];
    const int tid = threadIdx.x;
    const long row0 = (long)blockIdx.x * 64;
    if (tid < 64) {
        float m = st[tid] * INV_N;
        float var = fmaf(-m, m, st[64 + tid] * INV_N);
        float a = g1[tid] * rsqrtf(var + EPSF);
        sA[tid] = a; sC[tid] = fmaf(-m, a, b1[tid]);
    }
    __syncthreads();
    for (int i = tid; i < 4096; i += 256) {
        int r = i >> 6, kk = i & 63;
        sX[r][kk] = fmaxf(fmaf(T1[(row0 + r) * 64 + kk], sA[kk], sC[kk]), 0.f);
    }
    const int r = tid & 63, c0 = (tid >> 6) << 4;
    const float* Ws[3] = {Wq, Wk, Wv};
    const float* Bs[3] = {bq, bk, bv};
    float* Os[3] = {oq, ok, ov};
#pragma unroll 1
    for (int m = 0; m < 3; m++) {
        __syncthreads();
        for (int i = tid; i < 4096; i += 256) sW[i >> 6][i & 63] = Ws[m][i];
        __syncthreads();
        float acc[16];
#pragma unroll
        for (int j = 0; j < 16; j++) acc[j] = __ldg(&Bs[m][c0 + j]);
#pragma unroll
        for (int kk = 0; kk < 64; kk++) {
            float xv = sX[r][kk];
#pragma unroll
            for (int j = 0; j < 16; j++) acc[j] = fmaf(xv, sW[kk][c0 + j], acc[j]);
        }
        float* op = Os[m] + (row0 + r) * 64 + c0;
#pragma unroll
        for (int j = 0; j < 16; j++) op[j] = acc[j];
    }
}

// ---------------------------------------------------------------------------
// bnp param loader (computed from raw stats)
__device__ __forceinline__ void bnp_params(const float* st, const float* bnpg,
                                           const float* bnpb,
                                           float& A0, float& A1, float& A2,
                                           float& C0, float& C1, float& C2)
{
    float m0 = __ldg(&st[128]) * INV_P;
    A0 = __ldg(&bnpg[0]) * rsqrtf(fmaf(-m0, m0, __ldg(&st[136]) * INV_P) + EPSF);
    C0 = fmaf(-m0, A0, __ldg(&bnpb[0]));
    float m1 = __ldg(&st[129]) * INV_P;
    A1 = __ldg(&bnpg[1]) * rsqrtf(fmaf(-m1, m1, __ldg(&st[137]) * INV_P) + EPSF);
    C1 = fmaf(-m1, A1, __ldg(&bnpb[1]));
    float m2 = __ldg(&st[130]) * INV_P;
    A2 = __ldg(&bnpg[2]) * rsqrtf(fmaf(-m2, m2, __ldg(&st[138]) * INV_P) + EPSF);
    C2 = fmaf(-m2, A2, __ldg(&bnpb[2]));
}

// ---------------------------------------------------------------------------
// pass A: stats of w = k_g - q + pe. warp-per-point, float2 channels (2l,2l+1),
// pe stage-1 from cached U (bn+relu once per lane, shuffled per ns).
__global__ void __launch_bounds__(256) k_wstats(
        const int* __restrict__ knn,
        const float* __restrict__ Qm, const float* __restrict__ Km,
        const float4* __restrict__ U,
        const float* __restrict__ bnpg, const float* __restrict__ bnpb,
        const float* __restrict__ Wp2, const float* __restrict__ bp2,
        float* __restrict__ st)
{
    const int tid = threadIdx.x, lane = tid & 31;
    const int ch0 = lane * 2, ch1 = ch0 + 1;
    float A0,A1,A2,C0,C1,C2; bnp_params(st, bnpg, bnpb, A0,A1,A2,C0,C1,C2);
    float P00=__ldg(&Wp2[ch0]), P10=__ldg(&Wp2[64+ch0]), P20=__ldg(&Wp2[128+ch0]), B0=__ldg(&bp2[ch0]);
    float P01=__ldg(&Wp2[ch1]), P11=__ldg(&Wp2[64+ch1]), P21=__ldg(&Wp2[128+ch1]), B1=__ldg(&bp2[ch1]);
    float s0=0,q0=0,s1=0,q1=0;
    const int warp = (blockIdx.x * blockDim.x + tid) >> 5;
    const int nw = (gridDim.x * blockDim.x) >> 5;
    for (int n = warp; n < NPTS; n += nw) {
        float2 qv = ((const float2*)(Qm + (long)n*64))[lane];
        float qb0 = B0 - qv.x, qb1 = B1 - qv.y;
        int mk = 0; float t0 = 0.f, t1 = 0.f, t2 = 0.f;
        if (lane < 16) {
            mk = __ldg(&knn[n*16 + lane]);
            float4 uu = __ldg(&U[n*16 + lane]);
            t0 = fmaxf(fmaf(uu.x, A0, C0), 0.f);
            t1 = fmaxf(fmaf(uu.y, A1, C1), 0.f);
            t2 = fmaxf(fmaf(uu.z, A2, C2), 0.f);
        }
#pragma unroll 8
        for (int ns = 0; ns < 16; ns++) {
            int idx = __shfl_sync(0xffffffffu, mk, ns);
            float r0 = __shfl_sync(0xffffffffu, t0, ns);
            float r1 = __shfl_sync(0xffffffffu, t1, ns);
            float r2 = __shfl_sync(0xffffffffu, t2, ns);
            float pe0 = fmaf(r0,P00,fmaf(r1,P10,fmaf(r2,P20,qb0)));
            float pe1 = fmaf(r0,P01,fmaf(r1,P11,fmaf(r2,P21,qb1)));
            float2 kf = ((const float2*)(Km + (long)idx*64))[lane];
            float wv0 = kf.x + pe0;
            float wv1 = kf.y + pe1;
            s0 += wv0; q0 = fmaf(wv0,wv0,q0);
            s1 += wv1; q1 = fmaf(wv1,wv1,q1);
        }
    }
    __shared__ float sS[64], sQ[64];
    if (tid < 64) { sS[tid] = 0.f; sQ[tid] = 0.f; }
    __syncthreads();
    atomicAdd(&sS[ch0], s0); atomicAdd(&sQ[ch0], q0);
    atomicAdd(&sS[ch1], s1); atomicAdd(&sQ[ch1], q1);
    __syncthreads();
    if (tid < 64) {
        atomicAdd(&st[144 + tid], sS[tid]);
        atomicAdd(&st[208 + tid], sQ[tid]);
    }
}

// ---------------------------------------------------------------------------
// pass B: recompute w, bnw1+relu -> smem stage -> GEMV 64->8, fused bnw2 stats
__global__ void __launch_bounds__(256) k_passB(
        const int* __restrict__ knn,
        const float* __restrict__ Qm, const float* __restrict__ Km,
        const float4* __restrict__ U,
        const float* __restrict__ bnpg, const float* __restrict__ bnpb,
        const float* __restrict__ Wp2, const float* __restrict__ bp2,
        const float* __restrict__ g1, const float* __restrict__ b1,
        const float* __restrict__ Ww1, const float* __restrict__ bw1,
        float* __restrict__ w1out, float* __restrict__ st)
{
    __shared__ float sWw1[64][8];
    __shared__ float sBw[8];
    __shared__ float sWm[8][16][68];
    __shared__ float sS8[8], sQ8[8];
    const int tid = threadIdx.x, lane = tid & 31, wl = tid >> 5;
    for (int i = tid; i < 512; i += 256) sWw1[i >> 3][i & 7] = Ww1[i];
    if (tid < 8) { sBw[tid] = bw1[tid]; sS8[tid] = 0.f; sQ8[tid] = 0.f; }
    __syncthreads();
    const int ch0 = lane * 2, ch1 = ch0 + 1;
    float A0,A1,A2,C0,C1,C2; bnp_params(st, bnpg, bnpb, A0,A1,A2,C0,C1,C2);
    float P00=__ldg(&Wp2[ch0]), P10=__ldg(&Wp2[64+ch0]), P20=__ldg(&Wp2[128+ch0]), B0=__ldg(&bp2[ch0]);
    float P01=__ldg(&Wp2[ch1]), P11=__ldg(&Wp2[64+ch1]), P21=__ldg(&Wp2[128+ch1]), B1=__ldg(&bp2[ch1]);
    float m0 = __ldg(&st[144+ch0]) * INV_P;
    float Aa0 = __ldg(&g1[ch0]) * rsqrtf(fmaf(-m0, m0, __ldg(&st[208+ch0]) * INV_P) + EPSF);
    float Cc0 = fmaf(-m0, Aa0, __ldg(&b1[ch0]));
    float m1 = __ldg(&st[144+ch1]) * INV_P;
    float Aa1 = __ldg(&g1[ch1]) * rsqrtf(fmaf(-m1, m1, __ldg(&st[208+ch1]) * INV_P) + EPSF);
    float Cc1 = fmaf(-m1, Aa1, __ldg(&b1[ch1]));

    const int pair = lane >> 1, ob = (lane & 1) << 2;
    float sAcc[4] = {0,0,0,0}, qAcc[4] = {0,0,0,0};
    const int warp = (blockIdx.x * blockDim.x + tid) >> 5;
    const int nw = (gridDim.x * blockDim.x) >> 5;
    for (int n = warp; n < NPTS; n += nw) {
        float2 qv = ((const float2*)(Qm + (long)n*64))[lane];
        float qb0 = B0 - qv.x, qb1 = B1 - qv.y;
        int mk = 0; float t0 = 0.f, t1 = 0.f, t2 = 0.f;
        if (lane < 16) {
            mk = __ldg(&knn[n*16 + lane]);
            float4 uu = __ldg(&U[n*16 + lane]);
            t0 = fmaxf(fmaf(uu.x, A0, C0), 0.f);
            t1 = fmaxf(fmaf(uu.y, A1, C1), 0.f);
            t2 = fmaxf(fmaf(uu.z, A2, C2), 0.f);
        }
#pragma unroll 8
        for (int ns = 0; ns < 16; ns++) {
            int idx = __shfl_sync(0xffffffffu, mk, ns);
            float r0 = __shfl_sync(0xffffffffu, t0, ns);
            float r1 = __shfl_sync(0xffffffffu, t1, ns);
            float r2 = __shfl_sync(0xffffffffu, t2, ns);
            float pe0 = fmaf(r0,P00,fmaf(r1,P10,fmaf(r2,P20,qb0)));
            float pe1 = fmaf(r0,P01,fmaf(r1,P11,fmaf(r2,P21,qb1)));
            float2 kf = ((const float2*)(Km + (long)idx*64))[lane];
            float wv0 = kf.x + pe0;
            float wv1 = kf.y + pe1;
            float2 rw;
            rw.x = fmaxf(fmaf(wv0, Aa0, Cc0), 0.f);
            rw.y = fmaxf(fmaf(wv1, Aa1, Cc1), 0.f);
            *(float2*)&sWm[wl][ns][ch0] = rw;
        }
        __syncwarp();
        float a0=0.f, a1=0.f, a2=0.f, a3=0.f;
        const float* wrow = sWm[wl][pair];
#pragma unroll
        for (int c4 = 0; c4 < 16; c4++) {
            float4 wv = *(const float4*)&wrow[c4*4];
            float4 w0 = *(const float4*)&sWw1[c4*4+0][ob];
            float4 w1 = *(const float4*)&sWw1[c4*4+1][ob];
            float4 w2 = *(const float4*)&sWw1[c4*4+2][ob];
            float4 w3 = *(const float4*)&sWw1[c4*4+3][ob];
            a0 = fmaf(wv.x, w0.x, fmaf(wv.y, w1.x, fmaf(wv.z, w2.x, fmaf(wv.w, w3.x, a0))));
            a1 = fmaf(wv.x, w0.y, fmaf(wv.y, w1.y, fmaf(wv.z, w2.y, fmaf(wv.w, w3.y, a1))));
            a2 = fmaf(wv.x, w0.z, fmaf(wv.y, w1.z, fmaf(wv.z, w2.z, fmaf(wv.w, w3.z, a2))));
            a3 = fmaf(wv.x, w0.w, fmaf(wv.y, w1.w, fmaf(wv.z, w2.w, fmaf(wv.w, w3.w, a3))));
        }
        float4 t;
        t.x = a0 + sBw[ob+0]; t.y = a1 + sBw[ob+1];
        t.z = a2 + sBw[ob+2]; t.w = a3 + sBw[ob+3];
        ((float4*)(w1out + (long)n*128))[lane] = t;
        sAcc[0]+=t.x; qAcc[0]=fmaf(t.x,t.x,qAcc[0]);
        sAcc[1]+=t.y; qAcc[1]=fmaf(t.y,t.y,qAcc[1]);
        sAcc[2]+=t.z; qAcc[2]=fmaf(t.z,t.z,qAcc[2]);
        sAcc[3]+=t.w; qAcc[3]=fmaf(t.w,t.w,qAcc[3]);
        __syncwarp();
    }
#pragma unroll
    for (int off = 16; off >= 2; off >>= 1) {
#pragma unroll
        for (int j = 0; j < 4; j++) {
            sAcc[j] += __shfl_xor_sync(0xffffffffu, sAcc[j], off);
            qAcc[j] += __shfl_xor_sync(0xffffffffu, qAcc[j], off);
        }
    }
    if (lane < 2) {
#pragma unroll
        for (int j = 0; j < 4; j++) {
            atomicAdd(&sS8[ob + j], sAcc[j]);
            atomicAdd(&sQ8[ob + j], qAcc[j]);
        }
    }
    __syncthreads();
    if (tid < 8) {
        atomicAdd(&st[272 + tid], sS8[tid]);
        atomicAdd(&st[280 + tid], sQ8[tid]);
    }
}

// ---------------------------------------------------------------------------
// pass C: bnw2+relu -> logits -> softmax -> weighted (v_g+pe) agg, fused bn2 stats
// channel map (lane, lane+32) so both channels share output group o=lane&7.
__global__ void __launch_bounds__(256) k_passC(
        const int* __restrict__ knn,
        const float* __restrict__ Vm, const float* __restrict__ w1in,
        const float4* __restrict__ U,
        const float* __restrict__ bnpg, const float* __restrict__ bnpb,
        const float* __restrict__ Wp2, const float* __restrict__ bp2,
        const float* __restrict__ g2, const float* __restrict__ b2,
        const float* __restrict__ Ww2, const float* __restrict__ bw2,
        float* __restrict__ agg, float* __restrict__ st)
{
    __shared__ float sW2[8][8];
    __shared__ float sA8[8], sC8[8], sB8[8];
    __shared__ float wsm[8][8][16];   // [warp][o][ns]
    __shared__ float sS[64], sQ[64];
    const int tid = threadIdx.x, lane = tid & 31, wl = tid >> 5;
    if (tid < 64) { sW2[tid >> 3][tid & 7] = Ww2[tid]; sS[tid] = 0.f; sQ[tid] = 0.f; }
    if (tid < 8) {
        float m = st[272 + tid] * INV_P;
        float var = fmaf(-m, m, st[280 + tid] * INV_P);
        float a = g2[tid] * rsqrtf(var + EPSF);
        sA8[tid] = a; sC8[tid] = fmaf(-m, a, b2[tid]);
        sB8[tid] = bw2[tid];
    }
    __syncthreads();
    const int c0 = lane, c1 = lane + 32;
    float A0,A1,A2,C0,C1,C2; bnp_params(st, bnpg, bnpb, A0,A1,A2,C0,C1,C2);
    float P00=__ldg(&Wp2[c0]), P10=__ldg(&Wp2[64+c0]), P20=__ldg(&Wp2[128+c0]), B0=__ldg(&bp2[c0]);
    float P01=__ldg(&Wp2[c1]), P11=__ldg(&Wp2[64+c1]), P21=__ldg(&Wp2[128+c1]), B1=__ldg(&bp2[c1]);
    const int pair = lane >> 1, ob = (lane & 1) << 2;
    const int oo = lane & 7;
    float s0=0,q0=0,s1=0,q1=0;
    const int warp = (blockIdx.x * blockDim.x + tid) >> 5;
    const int nw = (gridDim.x * blockDim.x) >> 5;
    for (int n = warp; n < NPTS; n += nw) {
        // phase 1: logits
        {
            const float4* wp = (const float4*)(w1in + (long)n*128 + pair*8);
            float4 lo = wp[0], hi = wp[1];
            float rv[8] = {lo.x, lo.y, lo.z, lo.w, hi.x, hi.y, hi.z, hi.w};
#pragma unroll
            for (int i = 0; i < 8; i++) rv[i] = fmaxf(fmaf(rv[i], sA8[i], sC8[i]), 0.f);
#pragma unroll
            for (int j = 0; j < 4; j++) {
                int o = ob + j;
                float lg = sB8[o];
#pragma unroll
                for (int i = 0; i < 8; i++) lg = fmaf(rv[i], sW2[i][o], lg);
                wsm[wl][o][pair] = lg;
            }
        }
        __syncwarp();
        // phase 2: softmax over ns
        if (lane < 8) {
            float* row = wsm[wl][lane];
            float4 v0 = *(float4*)&row[0], v1 = *(float4*)&row[4];
            float4 v2 = *(float4*)&row[8], v3 = *(float4*)&row[12];
            float m = fmaxf(fmaxf(fmaxf(v0.x,v0.y),fmaxf(v0.z,v0.w)),
                     fmaxf(fmaxf(fmaxf(v1.x,v1.y),fmaxf(v1.z,v1.w)),
                     fmaxf(fmaxf(fmaxf(v2.x,v2.y),fmaxf(v2.z,v2.w)),
                           fmaxf(fmaxf(v3.x,v3.y),fmaxf(v3.z,v3.w)))));
            v0.x=__expf(v0.x-m); v0.y=__expf(v0.y-m); v0.z=__expf(v0.z-m); v0.w=__expf(v0.w-m);
            v1.x=__expf(v1.x-m); v1.y=__expf(v1.y-m); v1.z=__expf(v1.z-m); v1.w=__expf(v1.w-m);
            v2.x=__expf(v2.x-m); v2.y=__expf(v2.y-m); v2.z=__expf(v2.z-m); v2.w=__expf(v2.w-m);
            v3.x=__expf(v3.x-m); v3.y=__expf(v3.y-m); v3.z=__expf(v3.z-m); v3.w=__expf(v3.w-m);
            float ssum = (v0.x+v0.y+v0.z+v0.w)+(v1.x+v1.y+v1.z+v1.w)
                        +(v2.x+v2.y+v2.z+v2.w)+(v3.x+v3.y+v3.z+v3.w);
            float inv = 1.f / ssum;
            v0.x*=inv; v0.y*=inv; v0.z*=inv; v0.w*=inv;
            v1.x*=inv; v1.y*=inv; v1.z*=inv; v1.w*=inv;
            v2.x*=inv; v2.y*=inv; v2.z*=inv; v2.w*=inv;
            v3.x*=inv; v3.y*=inv; v3.z*=inv; v3.w*=inv;
            *(float4*)&row[0]=v0; *(float4*)&row[4]=v1;
            *(float4*)&row[8]=v2; *(float4*)&row[12]=v3;
        }
        __syncwarp();
        // phase 3: preload weights + u, aggregate over neighbors
        float wts[16];
        {
            const float4* wr = (const float4*)wsm[wl][oo];
#pragma unroll
            for (int t4 = 0; t4 < 4; t4++) {
                float4 v = wr[t4];
                wts[t4*4+0]=v.x; wts[t4*4+1]=v.y; wts[t4*4+2]=v.z; wts[t4*4+3]=v.w;
            }
        }
        int mk = 0; float t0 = 0.f, t1 = 0.f, t2 = 0.f;
        if (lane < 16) {
            mk = __ldg(&knn[n*16 + lane]);
            float4 uu = __ldg(&U[n*16 + lane]);
            t0 = fmaxf(fmaf(uu.x, A0, C0), 0.f);
            t1 = fmaxf(fmaf(uu.y, A1, C1), 0.f);
            t2 = fmaxf(fmaf(uu.z, A2, C2), 0.f);
        }
        float acc0 = 0.f, acc1 = 0.f;
#pragma unroll 8
        for (int ns = 0; ns < 16; ns++) {
            int idx = __shfl_sync(0xffffffffu, mk, ns);
            float r0 = __shfl_sync(0xffffffffu, t0, ns);
            float r1 = __shfl_sync(0xffffffffu, t1, ns);
            float r2 = __shfl_sync(0xffffffffu, t2, ns);
            float pe0 = fmaf(r0,P00,fmaf(r1,P10,fmaf(r2,P20,B0)));
            float pe1 = fmaf(r0,P01,fmaf(r1,P11,fmaf(r2,P21,B1)));
            long vo = (long)idx * 64;
            acc0 = fmaf(Vm[vo+c0] + pe0, wts[ns], acc0);
            acc1 = fmaf(Vm[vo+c1] + pe1, wts[ns], acc1);
        }
        agg[(long)n*64 + c0] = acc0;
        agg[(long)n*64 + c1] = acc1;
        s0 += acc0; q0 = fmaf(acc0,acc0,q0);
        s1 += acc1; q1 = fmaf(acc1,acc1,q1);
        __syncwarp();
    }
    atomicAdd(&sS[c0], s0); atomicAdd(&sQ[c0], q0);
    atomicAdd(&sS[c1], s1); atomicAdd(&sQ[c1], q1);
    __syncthreads();
    if (tid < 64) {
        atomicAdd(&st[288 + tid], sS[tid]);
        atomicAdd(&st[352 + tid], sQ[tid]);
    }
}

// ---------------------------------------------------------------------------
// gemm3: t3 = relu(bn2(agg)) @ W3, fused bn3 stats
__global__ void __launch_bounds__(256) k_gemm3(
        const float* __restrict__ X, const float* __restrict__ W,
        const float* __restrict__ st, const float* __restrict__ bg,
        const float* __restrict__ bb, float* __restrict__ out, float* __restrict__ sto)
{
    __shared__ float sX[64][65];
    __shared__ float sW[64][64];
    __shared__ float sA[64], sC[64];
    __shared__ float sS[64], sQ[64];
    const int tid = threadIdx.x;
    const long row0 = (long)blockIdx.x * 64;
    if (tid < 64) {
        sS[tid] = 0.f; sQ[tid] = 0.f;
        float m = st[288 + tid] * INV_N;
        float var = fmaf(-m, m, st[352 + tid] * INV_N);
        float a = bg[tid] * rsqrtf(var + EPSF);
        sA[tid] = a; sC[tid] = fmaf(-m, a, bb[tid]);
    }
    for (int i = tid; i < 4096; i += 256) sW[i >> 6][i & 63] = W[i];
    __syncthreads();
    for (int i = tid; i < 4096; i += 256) {
        int r = i >> 6, kk = i & 63;
        sX[r][kk] = fmaxf(fmaf(X[(row0 + r) * 64 + kk], sA[kk], sC[kk]), 0.f);
    }
    __syncthreads();
    const int lane = tid & 31;
    const int r = tid & 63, c0 = (tid >> 6) << 4;
    float acc[16];
#pragma unroll
    for (int j = 0; j < 16; j++) acc[j] = 0.f;
#pragma unroll
    for (int kk = 0; kk < 64; kk++) {
        float xv = sX[r][kk];
#pragma unroll
        for (int j = 0; j < 16; j++) acc[j] = fmaf(xv, sW[kk][c0 + j], acc[j]);
    }
    float* op = out + (row0 + r) * 64 + c0;
#pragma unroll
    for (int j = 0; j < 16; j++) op[j] = acc[j];
#pragma unroll
    for (int j = 0; j < 16; j++) {
        float s = acc[j], q = acc[j] * acc[j];
#pragma unroll
        for (int off = 16; off; off >>= 1) {
            s += __shfl_xor_sync(0xffffffffu, s, off);
            q += __shfl_xor_sync(0xffffffffu, q, off);
        }
        if (lane == 0) { atomicAdd(&sS[c0 + j], s); atomicAdd(&sQ[c0 + j], q); }
    }
    __syncthreads();
    if (tid < 64) {
        atomicAdd(&sto[416 + tid], sS[tid]);
        atomicAdd(&sto[480 + tid], sQ[tid]);
    }
}

// out = relu(bn3(t3) + x), bn3 params inline
__global__ void k_final(const float* __restrict__ T3, const float* __restrict__ X,
                        const float* __restrict__ st,
                        const float* __restrict__ g3, const float* __restrict__ b3,
                        float* __restrict__ out)
{
    __shared__ float sA[64], sC[64];
    const int tid = threadIdx.x;
    if (tid < 64) {
        float m = st[416 + tid] * INV_N;
        float var = fmaf(-m, m, st[480 + tid] * INV_N);
        float a = g3[tid] * rsqrtf(var + EPSF);
        sA[tid] = a; sC[tid] = fmaf(-m, a, b3[tid]);
    }
    __syncthreads();
    const int stride = gridDim.x * blockDim.x;
    for (int i = blockIdx.x * blockDim.x + tid; i < NPTS * 16; i += stride) {
        int cb = (i * 4) & 63;
        float4 t = ((const float4*)T3)[i];
        float4 x4 = ((const float4*)X)[i];
        float4 r;
        r.x = fmaxf(fmaf(t.x, sA[cb+0], sC[cb+0]) + x4.x, 0.f);
        r.y = fmaxf(fmaf(t.y, sA[cb+1], sC[cb+1]) + x4.y, 0.f);
        r.z = fmaxf(fmaf(t.z, sA[cb+2], sC[cb+2]) + x4.z, 0.f);
        r.w = fmaxf(fmaf(t.w, sA[cb+3], sC[cb+3]) + x4.w, 0.f);
        ((float4*)out)[i] = r;
    }
}

// ---------------------------------------------------------------------------
extern "C" void kernel_launch(void* const* d_in, const int* in_sizes, int n_in,
                              void* d_out, int out_size)
{
    const float* p     = (const float*)d_in[0];
    const float* x     = (const float*)d_in[1];
    const int*   knn   = (const int*)  d_in[2];
    const float* W1    = (const float*)d_in[3];
    const float* bn1g  = (const float*)d_in[4];
    const float* bn1b  = (const float*)d_in[5];
    const float* Wq    = (const float*)d_in[6];
    const float* bq    = (const float*)d_in[7];
    const float* Wk    = (const float*)d_in[8];
    const float* bk    = (const float*)d_in[9];
    const float* Wv    = (const float*)d_in[10];
    const float* bv    = (const float*)d_in[11];
    const float* Wp1   = (const float*)d_in[12];
    const float* bp1   = (const float*)d_in[13];
    const float* bnpg  = (const float*)d_in[14];
    const float* bnpb  = (const float*)d_in[15];
    const float* Wp2   = (const float*)d_in[16];
    const float* bp2   = (const float*)d_in[17];
    const float* bnw1g = (const float*)d_in[18];
    const float* bnw1b = (const float*)d_in[19];
    const float* Ww1   = (const float*)d_in[20];
    const float* bw1   = (const float*)d_in[21];
    const float* bnw2g = (const float*)d_in[22];
    const float* bnw2b = (const float*)d_in[23];
    const float* Ww2   = (const float*)d_in[24];
    const float* bw2   = (const float*)d_in[25];
    const float* bn2g  = (const float*)d_in[26];
    const float* bn2b  = (const float*)d_in[27];
    const float* W3    = (const float*)d_in[28];
    const float* bn3g  = (const float*)d_in[29];
    const float* bn3b  = (const float*)d_in[30];
    float* out = (float*)d_out;

    float* scr = nullptr;
    cudaGetSymbolAddress((void**)&scr, g_scr);
    float* t1  = scr + OFF_T1;
    float* qb  = scr + OFF_Q;
    float* kb  = scr + OFF_K;
    float* vb  = scr + OFF_V;
    float* w1b = scr + OFF_W1B;
    float* agg = scr + OFF_AGG;
    float* t3  = scr + OFF_T3;
    float4* U  = (float4*)(scr + OFF_U);
    float* st  = scr + OFF_STATS;

    k_zero<<<1, 544>>>(st);

    // gemm1 + pstats (heterogeneous grid, overlapped)
    k_g1p<<<GEMM_BLOCKS + PST_BLOCKS, 256>>>(x, W1, t1, st, p, knn, Wp1, bp1, U);

    // q,k,v (bn1 inline)
    k_qkv<<<1250, 256>>>(t1, Wq, bq, Wk, bk, Wv, bv, st, bn1g, bn1b, qb, kb, vb);

    // bnw1 stats
    k_wstats<<<1184, 256>>>(knn, qb, kb, U, bnpg, bnpb, Wp2, bp2, st);

    // pass B (+ bnw2 stats)
    k_passB<<<888, 256>>>(knn, qb, kb, U, bnpg, bnpb, Wp2, bp2,
                          bnw1g, bnw1b, Ww1, bw1, w1b, st);

    // pass C (+ bn2 stats)
    k_passC<<<1184, 256>>>(knn, vb, w1b, U, bnpg, bnpb, Wp2, bp2,
                           bnw2g, bnw2b, Ww2, bw2, agg, st);

    // gemm3 (bn2 inline, + bn3 stats)
    k_gemm3<<<1250, 256>>>(agg, W3, st, bn2g, bn2b, t3, st);

    // residual + relu (bn3 inline)
    k_final<<<640, 256>>>(t3, x, st, bn3g, bn3b, out);
}

// round 4
// speedup vs baseline: 1.9789x; 1.1389x over previous
#include <cuda_runtime.h>

#define NPTS 80000
#define NSAMP 16
#define PAIRS (NPTS*NSAMP)
#define EPSF 1e-5f
#define INV_N (1.0f/80000.0f)
#define INV_P (1.0f/1280000.0f)
#define GEMM_BLOCKS 1250
#define PST_BLOCKS  1024

// ---------------- scratch (device-global) ----------------
#define OFF_T1    0
#define OFF_Q     5120000
#define OFF_K     10240000
#define OFF_V     15360000
#define OFF_W1B   20480000
#define OFF_AGG   30720000
#define OFF_T3    35840000
#define OFF_U     40960000           /* float4 per pair: u0,u1,u2,pad */
#define OFF_STATS 46080000
__device__ float g_scr[46080640];

// stats sublayout:
//  +0   bn1 sum(64)   | +64  bn1 sq(64)
//  +128 bnp sum(3)    | +136 bnp sq(3)
//  +144 bnw1 sum(64)  | +208 bnw1 sq(64)
//  +272 bnw2 sum(8)   | +280 bnw2 sq(8)
//  +288 bn2 sum(64)   | +352 bn2 sq(64)
//  +416 bn3 sum(64)   | +480 bn3 sq(64)

__global__ void k_zero(float* st) { int i = threadIdx.x; if (i < 544) st[i] = 0.f; }

// ---------------------------------------------------------------------------
// heterogeneous: blocks [0,1250) = gemm1 (t1 = x@W1, fused bn1 stats);
//                blocks [1250,2274) = pstats (+ u store)
__global__ void __launch_bounds__(256) k_g1p(
        const float* __restrict__ X, const float* __restrict__ W,
        float* __restrict__ out, float* __restrict__ st,
        const float* __restrict__ p, const int* __restrict__ knn,
        const float* __restrict__ Wp1, const float* __restrict__ bp1,
        float4* __restrict__ U)
{
    const int tid = threadIdx.x;
    if (blockIdx.x < GEMM_BLOCKS) {
        __shared__ float sX[64][65];
        __shared__ float sW[64][64];
        __shared__ float sS[64], sQ[64];
        const long row0 = (long)blockIdx.x * 64;
        if (tid < 64) { sS[tid] = 0.f; sQ[tid] = 0.f; }
        for (int i = tid; i < 4096; i += 256) sW[i >> 6][i & 63] = W[i];
        for (int i = tid; i < 4096; i += 256) {
            int r = i >> 6, kk = i & 63;
            sX[r][kk] = X[(row0 + r) * 64 + kk];
        }
        __syncthreads();
        const int lane = tid & 31;
        const int r = tid & 63, c0 = (tid >> 6) << 4;
        float acc[16];
#pragma unroll
        for (int j = 0; j < 16; j++) acc[j] = 0.f;
#pragma unroll
        for (int kk = 0; kk < 64; kk++) {
            float xv = sX[r][kk];
#pragma unroll
            for (int j = 0; j < 16; j++) acc[j] = fmaf(xv, sW[kk][c0 + j], acc[j]);
        }
        float* op = out + (row0 + r) * 64 + c0;
#pragma unroll
        for (int j = 0; j < 16; j++) op[j] = acc[j];
#pragma unroll
        for (int j = 0; j < 16; j++) {
            float s = acc[j], q = acc[j] * acc[j];
#pragma unroll
            for (int off = 16; off; off >>= 1) {
                s += __shfl_xor_sync(0xffffffffu, s, off);
                q += __shfl_xor_sync(0xffffffffu, q, off);
            }
            if (lane == 0) { atomicAdd(&sS[c0 + j], s); atomicAdd(&sQ[c0 + j], q); }
        }
        __syncthreads();
        if (tid < 64) {
            atomicAdd(&st[tid], sS[tid]);
            atomicAdd(&st[64 + tid], sQ[tid]);
        }
    } else {
        float w[9], bb[3];
#pragma unroll
        for (int i = 0; i < 9; i++) w[i] = __ldg(&Wp1[i]);
#pragma unroll
        for (int j = 0; j < 3; j++) bb[j] = __ldg(&bp1[j]);
        float s0=0,s1=0,s2=0,q0=0,q1=0,q2=0;
        const int bid = blockIdx.x - GEMM_BLOCKS;
        const int stride = PST_BLOCKS * 256;
        for (int pr = bid * 256 + tid; pr < PAIRS; pr += stride) {
            int n = pr >> 4;
            int idx = __ldg(&knn[pr]);
            float ax = p[idx*3+0]-p[n*3+0];
            float ay = p[idx*3+1]-p[n*3+1];
            float az = p[idx*3+2]-p[n*3+2];
            float u0 = fmaf(ax,w[0],fmaf(ay,w[3],fmaf(az,w[6],bb[0])));
            float u1 = fmaf(ax,w[1],fmaf(ay,w[4],fmaf(az,w[7],bb[1])));
            float u2 = fmaf(ax,w[2],fmaf(ay,w[5],fmaf(az,w[8],bb[2])));
            U[pr] = make_float4(u0, u1, u2, 0.f);
            s0+=u0; s1+=u1; s2+=u2;
            q0=fmaf(u0,u0,q0); q1=fmaf(u1,u1,q1); q2=fmaf(u2,u2,q2);
        }
#pragma unroll
        for (int off = 16; off; off >>= 1) {
            s0 += __shfl_xor_sync(0xffffffffu, s0, off);
            s1 += __shfl_xor_sync(0xffffffffu, s1, off);
            s2 += __shfl_xor_sync(0xffffffffu, s2, off);
            q0 += __shfl_xor_sync(0xffffffffu, q0, off);
            q1 += __shfl_xor_sync(0xffffffffu, q1, off);
            q2 += __shfl_xor_sync(0xffffffffu, q2, off);
        }
        __shared__ float sm[6];
        if (tid < 6) sm[tid] = 0.f;
        __syncthreads();
        if ((tid & 31) == 0) {
            atomicAdd(&sm[0], s0); atomicAdd(&sm[1], s1); atomicAdd(&sm[2], s2);
            atomicAdd(&sm[3], q0); atomicAdd(&sm[4], q1); atomicAdd(&sm[5], q2);
        }
        __syncthreads();
        if (tid < 3) {
            atomicAdd(&st[128 + tid], sm[tid]);
            atomicAdd(&st[136 + tid], sm[3 + tid]);
        }
    }
}

// q/k/v fused, bn1 params inline from raw stats
__global__ void k_qkv(const float* __restrict__ T1,
                      const float* __restrict__ Wq, const float* __restrict__ bq,
                      const float* __restrict__ Wk, const float* __restrict__ bk,
                      const float* __restrict__ Wv, const float* __restrict__ bv,
                      const float* __restrict__ st,
                      const float* __restrict__ g1, const float* __restrict__ b1,
                      float* __restrict__ oq, float* __restrict__ ok, float* __restrict__ ov)
{
    __shared__ float sX[64][65];
    __shared__ float sW[64][64];
    __shared__ float sA[64], sC[64];
    const int tid = threadIdx.x;
    const long row0 = (long)blockIdx.x * 64;
    if (tid < 64) {
        float m = st[tid] * INV_N;
        float var = fmaf(-m, m, st[64 + tid] * INV_N);
        float a = g1[tid] * rsqrtf(var + EPSF);
        sA[tid] = a; sC[tid] = fmaf(-m, a, b1[tid]);
    }
    __syncthreads();
    for (int i = tid; i < 4096; i += 256) {
        int r = i >> 6, kk = i & 63;
        sX[r][kk] = fmaxf(fmaf(T1[(row0 + r) * 64 + kk], sA[kk], sC[kk]), 0.f);
    }
    const int r = tid & 63, c0 = (tid >> 6) << 4;
    const float* Ws[3] = {Wq, Wk, Wv};
    const float* Bs[3] = {bq, bk, bv};
    float* Os[3] = {oq, ok, ov};
#pragma unroll 1
    for (int m = 0; m < 3; m++) {
        __syncthreads();
        for (int i = tid; i < 4096; i += 256) sW[i >> 6][i & 63] = Ws[m][i];
        __syncthreads();
        float acc[16];
#pragma unroll
        for (int j = 0; j < 16; j++) acc[j] = __ldg(&Bs[m][c0 + j]);
#pragma unroll
        for (int kk = 0; kk < 64; kk++) {
            float xv = sX[r][kk];
#pragma unroll
            for (int j = 0; j < 16; j++) acc[j] = fmaf(xv, sW[kk][c0 + j], acc[j]);
        }
        float* op = Os[m] + (row0 + r) * 64 + c0;
#pragma unroll
        for (int j = 0; j < 16; j++) op[j] = acc[j];
    }
}

// ---------------------------------------------------------------------------
__device__ __forceinline__ void bnp_params(const float* st, const float* bnpg,
                                           const float* bnpb,
                                           float& A0, float& A1, float& A2,
                                           float& C0, float& C1, float& C2)
{
    float m0 = __ldg(&st[128]) * INV_P;
    A0 = __ldg(&bnpg[0]) * rsqrtf(fmaf(-m0, m0, __ldg(&st[136]) * INV_P) + EPSF);
    C0 = fmaf(-m0, A0, __ldg(&bnpb[0]));
    float m1 = __ldg(&st[129]) * INV_P;
    A1 = __ldg(&bnpg[1]) * rsqrtf(fmaf(-m1, m1, __ldg(&st[137]) * INV_P) + EPSF);
    C1 = fmaf(-m1, A1, __ldg(&bnpb[1]));
    float m2 = __ldg(&st[130]) * INV_P;
    A2 = __ldg(&bnpg[2]) * rsqrtf(fmaf(-m2, m2, __ldg(&st[138]) * INV_P) + EPSF);
    C2 = fmaf(-m2, A2, __ldg(&bnpb[2]));
}

// stage (idx, relu(bn(u))) for 16 neighbors of point n into smem (lanes 0..15)
__device__ __forceinline__ void stage_nb(float4* row, int n, int lane,
                                         const int* __restrict__ knn,
                                         const float4* __restrict__ U,
                                         float A0, float A1, float A2,
                                         float C0, float C1, float C2)
{
    if (lane < 16) {
        int mk = __ldg(&knn[n*16 + lane]);
        float4 uu = __ldg(&U[n*16 + lane]);
        float t0 = fmaxf(fmaf(uu.x, A0, C0), 0.f);
        float t1 = fmaxf(fmaf(uu.y, A1, C1), 0.f);
        float t2 = fmaxf(fmaf(uu.z, A2, C2), 0.f);
        row[lane] = make_float4(__int_as_float(mk), t0, t1, t2);
    }
    __syncwarp();
}

// ---------------------------------------------------------------------------
// pass A: stats of w = k_g - q + pe. warp-per-point, float2 channels (2l,2l+1).
__global__ void __launch_bounds__(256) k_wstats(
        const int* __restrict__ knn,
        const float* __restrict__ Qm, const float* __restrict__ Km,
        const float4* __restrict__ U,
        const float* __restrict__ bnpg, const float* __restrict__ bnpb,
        const float* __restrict__ Wp2, const float* __restrict__ bp2,
        float* __restrict__ st)
{
    __shared__ float4 sNb[8][16];
    const int tid = threadIdx.x, lane = tid & 31, wl = tid >> 5;
    const int ch0 = lane * 2, ch1 = ch0 + 1;
    float A0,A1,A2,C0,C1,C2; bnp_params(st, bnpg, bnpb, A0,A1,A2,C0,C1,C2);
    float P00=__ldg(&Wp2[ch0]), P10=__ldg(&Wp2[64+ch0]), P20=__ldg(&Wp2[128+ch0]), B0=__ldg(&bp2[ch0]);
    float P01=__ldg(&Wp2[ch1]), P11=__ldg(&Wp2[64+ch1]), P21=__ldg(&Wp2[128+ch1]), B1=__ldg(&bp2[ch1]);
    float s0=0,q0=0,s1=0,q1=0;
    const int warp = (blockIdx.x * blockDim.x + tid) >> 5;
    const int nw = (gridDim.x * blockDim.x) >> 5;
    for (int n = warp; n < NPTS; n += nw) {
        float2 qv = ((const float2*)(Qm + (long)n*64))[lane];
        float qb0 = B0 - qv.x, qb1 = B1 - qv.y;
        stage_nb(sNb[wl], n, lane, knn, U, A0,A1,A2, C0,C1,C2);
#pragma unroll
        for (int nb = 0; nb < 4; nb++) {
            float4 d0 = sNb[wl][nb*4+0];
            float4 d1 = sNb[wl][nb*4+1];
            float4 d2 = sNb[wl][nb*4+2];
            float4 d3 = sNb[wl][nb*4+3];
            float2 kf0 = ((const float2*)(Km + (long)__float_as_int(d0.x)*64))[lane];
            float2 kf1 = ((const float2*)(Km + (long)__float_as_int(d1.x)*64))[lane];
            float2 kf2 = ((const float2*)(Km + (long)__float_as_int(d2.x)*64))[lane];
            float2 kf3 = ((const float2*)(Km + (long)__float_as_int(d3.x)*64))[lane];
            float wv;
            wv = kf0.x + fmaf(d0.y,P00,fmaf(d0.z,P10,fmaf(d0.w,P20,qb0)));
            s0 += wv; q0 = fmaf(wv,wv,q0);
            wv = kf0.y + fmaf(d0.y,P01,fmaf(d0.z,P11,fmaf(d0.w,P21,qb1)));
            s1 += wv; q1 = fmaf(wv,wv,q1);
            wv = kf1.x + fmaf(d1.y,P00,fmaf(d1.z,P10,fmaf(d1.w,P20,qb0)));
            s0 += wv; q0 = fmaf(wv,wv,q0);
            wv = kf1.y + fmaf(d1.y,P01,fmaf(d1.z,P11,fmaf(d1.w,P21,qb1)));
            s1 += wv; q1 = fmaf(wv,wv,q1);
            wv = kf2.x + fmaf(d2.y,P00,fmaf(d2.z,P10,fmaf(d2.w,P20,qb0)));
            s0 += wv; q0 = fmaf(wv,wv,q0);
            wv = kf2.y + fmaf(d2.y,P01,fmaf(d2.z,P11,fmaf(d2.w,P21,qb1)));
            s1 += wv; q1 = fmaf(wv,wv,q1);
            wv = kf3.x + fmaf(d3.y,P00,fmaf(d3.z,P10,fmaf(d3.w,P20,qb0)));
            s0 += wv; q0 = fmaf(wv,wv,q0);
            wv = kf3.y + fmaf(d3.y,P01,fmaf(d3.z,P11,fmaf(d3.w,P21,qb1)));
            s1 += wv; q1 = fmaf(wv,wv,q1);
        }
        __syncwarp();
    }
    __shared__ float sS[64], sQ[64];
    if (tid < 64) { sS[tid] = 0.f; sQ[tid] = 0.f; }
    __syncthreads();
    atomicAdd(&sS[ch0], s0); atomicAdd(&sQ[ch0], q0);
    atomicAdd(&sS[ch1], s1); atomicAdd(&sQ[ch1], q1);
    __syncthreads();
    if (tid < 64) {
        atomicAdd(&st[144 + tid], sS[tid]);
        atomicAdd(&st[208 + tid], sQ[tid]);
    }
}

// ---------------------------------------------------------------------------
// pass B: recompute w, bnw1+relu -> smem stage -> GEMV 64->8, fused bnw2 stats
__global__ void __launch_bounds__(256) k_passB(
        const int* __restrict__ knn,
        const float* __restrict__ Qm, const float* __restrict__ Km,
        const float4* __restrict__ U,
        const float* __restrict__ bnpg, const float* __restrict__ bnpb,
        const float* __restrict__ Wp2, const float* __restrict__ bp2,
        const float* __restrict__ g1, const float* __restrict__ b1,
        const float* __restrict__ Ww1, const float* __restrict__ bw1,
        float* __restrict__ w1out, float* __restrict__ st)
{
    __shared__ float sWw1[64][8];
    __shared__ float sBw[8];
    __shared__ float sWm[8][16][68];
    __shared__ float4 sNb[8][16];
    __shared__ float sS8[8], sQ8[8];
    const int tid = threadIdx.x, lane = tid & 31, wl = tid >> 5;
    for (int i = tid; i < 512; i += 256) sWw1[i >> 3][i & 7] = Ww1[i];
    if (tid < 8) { sBw[tid] = bw1[tid]; sS8[tid] = 0.f; sQ8[tid] = 0.f; }
    __syncthreads();
    const int ch0 = lane * 2, ch1 = ch0 + 1;
    float A0,A1,A2,C0,C1,C2; bnp_params(st, bnpg, bnpb, A0,A1,A2,C0,C1,C2);
    float P00=__ldg(&Wp2[ch0]), P10=__ldg(&Wp2[64+ch0]), P20=__ldg(&Wp2[128+ch0]), B0=__ldg(&bp2[ch0]);
    float P01=__ldg(&Wp2[ch1]), P11=__ldg(&Wp2[64+ch1]), P21=__ldg(&Wp2[128+ch1]), B1=__ldg(&bp2[ch1]);
    float m0 = __ldg(&st[144+ch0]) * INV_P;
    float Aa0 = __ldg(&g1[ch0]) * rsqrtf(fmaf(-m0, m0, __ldg(&st[208+ch0]) * INV_P) + EPSF);
    float Cc0 = fmaf(-m0, Aa0, __ldg(&b1[ch0]));
    float m1 = __ldg(&st[144+ch1]) * INV_P;
    float Aa1 = __ldg(&g1[ch1]) * rsqrtf(fmaf(-m1, m1, __ldg(&st[208+ch1]) * INV_P) + EPSF);
    float Cc1 = fmaf(-m1, Aa1, __ldg(&b1[ch1]));

    const int pair = lane >> 1, ob = (lane & 1) << 2;
    float sAcc[4] = {0,0,0,0}, qAcc[4] = {0,0,0,0};
    const int warp = (blockIdx.x * blockDim.x + tid) >> 5;
    const int nw = (gridDim.x * blockDim.x) >> 5;
    for (int n = warp; n < NPTS; n += nw) {
        float2 qv = ((const float2*)(Qm + (long)n*64))[lane];
        float qb0 = B0 - qv.x, qb1 = B1 - qv.y;
        stage_nb(sNb[wl], n, lane, knn, U, A0,A1,A2, C0,C1,C2);
#pragma unroll
        for (int nb = 0; nb < 4; nb++) {
            float4 d0 = sNb[wl][nb*4+0];
            float4 d1 = sNb[wl][nb*4+1];
            float4 d2 = sNb[wl][nb*4+2];
            float4 d3 = sNb[wl][nb*4+3];
            float2 kf0 = ((const float2*)(Km + (long)__float_as_int(d0.x)*64))[lane];
            float2 kf1 = ((const float2*)(Km + (long)__float_as_int(d1.x)*64))[lane];
            float2 kf2 = ((const float2*)(Km + (long)__float_as_int(d2.x)*64))[lane];
            float2 kf3 = ((const float2*)(Km + (long)__float_as_int(d3.x)*64))[lane];
            float2 rw;
            rw.x = fmaxf(fmaf(kf0.x + fmaf(d0.y,P00,fmaf(d0.z,P10,fmaf(d0.w,P20,qb0))), Aa0, Cc0), 0.f);
            rw.y = fmaxf(fmaf(kf0.y + fmaf(d0.y,P01,fmaf(d0.z,P11,fmaf(d0.w,P21,qb1))), Aa1, Cc1), 0.f);
            *(float2*)&sWm[wl][nb*4+0][ch0] = rw;
            rw.x = fmaxf(fmaf(kf1.x + fmaf(d1.y,P00,fmaf(d1.z,P10,fmaf(d1.w,P20,qb0))), Aa0, Cc0), 0.f);
            rw.y = fmaxf(fmaf(kf1.y + fmaf(d1.y,P01,fmaf(d1.z,P11,fmaf(d1.w,P21,qb1))), Aa1, Cc1), 0.f);
            *(float2*)&sWm[wl][nb*4+1][ch0] = rw;
            rw.x = fmaxf(fmaf(kf2.x + fmaf(d2.y,P00,fmaf(d2.z,P10,fmaf(d2.w,P20,qb0))), Aa0, Cc0), 0.f);
            rw.y = fmaxf(fmaf(kf2.y + fmaf(d2.y,P01,fmaf(d2.z,P11,fmaf(d2.w,P21,qb1))), Aa1, Cc1), 0.f);
            *(float2*)&sWm[wl][nb*4+2][ch0] = rw;
            rw.x = fmaxf(fmaf(kf3.x + fmaf(d3.y,P00,fmaf(d3.z,P10,fmaf(d3.w,P20,qb0))), Aa0, Cc0), 0.f);
            rw.y = fmaxf(fmaf(kf3.y + fmaf(d3.y,P01,fmaf(d3.z,P11,fmaf(d3.w,P21,qb1))), Aa1, Cc1), 0.f);
            *(float2*)&sWm[wl][nb*4+3][ch0] = rw;
        }
        __syncwarp();
        float a0=0.f, a1=0.f, a2=0.f, a3=0.f;
        const float* wrow = sWm[wl][pair];
#pragma unroll
        for (int c4 = 0; c4 < 16; c4++) {
            float4 wv = *(const float4*)&wrow[c4*4];
            float4 w0 = *(const float4*)&sWw1[c4*4+0][ob];
            float4 w1 = *(const float4*)&sWw1[c4*4+1][ob];
            float4 w2 = *(const float4*)&sWw1[c4*4+2][ob];
            float4 w3 = *(const float4*)&sWw1[c4*4+3][ob];
            a0 = fmaf(wv.x, w0.x, fmaf(wv.y, w1.x, fmaf(wv.z, w2.x, fmaf(wv.w, w3.x, a0))));
            a1 = fmaf(wv.x, w0.y, fmaf(wv.y, w1.y, fmaf(wv.z, w2.y, fmaf(wv.w, w3.y, a1))));
            a2 = fmaf(wv.x, w0.z, fmaf(wv.y, w1.z, fmaf(wv.z, w2.z, fmaf(wv.w, w3.z, a2))));
            a3 = fmaf(wv.x, w0.w, fmaf(wv.y, w1.w, fmaf(wv.z, w2.w, fmaf(wv.w, w3.w, a3))));
        }
        float4 t;
        t.x = a0 + sBw[ob+0]; t.y = a1 + sBw[ob+1];
        t.z = a2 + sBw[ob+2]; t.w = a3 + sBw[ob+3];
        ((float4*)(w1out + (long)n*128))[lane] = t;
        sAcc[0]+=t.x; qAcc[0]=fmaf(t.x,t.x,qAcc[0]);
        sAcc[1]+=t.y; qAcc[1]=fmaf(t.y,t.y,qAcc[1]);
        sAcc[2]+=t.z; qAcc[2]=fmaf(t.z,t.z,qAcc[2]);
        sAcc[3]+=t.w; qAcc[3]=fmaf(t.w,t.w,qAcc[3]);
        __syncwarp();
    }
#pragma unroll
    for (int off = 16; off >= 2; off >>= 1) {
#pragma unroll
        for (int j = 0; j < 4; j++) {
            sAcc[j] += __shfl_xor_sync(0xffffffffu, sAcc[j], off);
            qAcc[j] += __shfl_xor_sync(0xffffffffu, qAcc[j], off);
        }
    }
    if (lane < 2) {
#pragma unroll
        for (int j = 0; j < 4; j++) {
            atomicAdd(&sS8[ob + j], sAcc[j]);
            atomicAdd(&sQ8[ob + j], qAcc[j]);
        }
    }
    __syncthreads();
    if (tid < 8) {
        atomicAdd(&st[272 + tid], sS8[tid]);
        atomicAdd(&st[280 + tid], sQ8[tid]);
    }
}

// ---------------------------------------------------------------------------
// pass C: bnw2+relu -> logits -> softmax -> weighted (v_g+pe) agg, fused bn2 stats
__global__ void __launch_bounds__(256) k_passC(
        const int* __restrict__ knn,
        const float* __restrict__ Vm, const float* __restrict__ w1in,
        const float4* __restrict__ U,
        const float* __restrict__ bnpg, const float* __restrict__ bnpb,
        const float* __restrict__ Wp2, const float* __restrict__ bp2,
        const float* __restrict__ g2, const float* __restrict__ b2,
        const float* __restrict__ Ww2, const float* __restrict__ bw2,
        float* __restrict__ agg, float* __restrict__ st)
{
    __shared__ float sW2[8][8];
    __shared__ float sA8[8], sC8[8], sB8[8];
    __shared__ float wsm[8][8][16];   // [warp][o][ns]
    __shared__ float4 sNb[8][16];
    __shared__ float sS[64], sQ[64];
    const int tid = threadIdx.x, lane = tid & 31, wl = tid >> 5;
    if (tid < 64) { sW2[tid >> 3][tid & 7] = Ww2[tid]; sS[tid] = 0.f; sQ[tid] = 0.f; }
    if (tid < 8) {
        float m = st[272 + tid] * INV_P;
        float var = fmaf(-m, m, st[280 + tid] * INV_P);
        float a = g2[tid] * rsqrtf(var + EPSF);
        sA8[tid] = a; sC8[tid] = fmaf(-m, a, b2[tid]);
        sB8[tid] = bw2[tid];
    }
    __syncthreads();
    const int c0 = lane, c1 = lane + 32;
    float A0,A1,A2,C0,C1,C2; bnp_params(st, bnpg, bnpb, A0,A1,A2,C0,C1,C2);
    float P00=__ldg(&Wp2[c0]), P10=__ldg(&Wp2[64+c0]), P20=__ldg(&Wp2[128+c0]), B0=__ldg(&bp2[c0]);
    float P01=__ldg(&Wp2[c1]), P11=__ldg(&Wp2[64+c1]), P21=__ldg(&Wp2[128+c1]), B1=__ldg(&bp2[c1]);
    const int pair = lane >> 1, ob = (lane & 1) << 2;
    const int oo = lane & 7;
    float s0=0,q0=0,s1=0,q1=0;
    const int warp = (blockIdx.x * blockDim.x + tid) >> 5;
    const int nw = (gridDim.x * blockDim.x) >> 5;
    for (int n = warp; n < NPTS; n += nw) {
        // phase 1: logits
        {
            const float4* wp = (const float4*)(w1in + (long)n*128 + pair*8);
            float4 lo = wp[0], hi = wp[1];
            float rv[8] = {lo.x, lo.y, lo.z, lo.w, hi.x, hi.y, hi.z, hi.w};
#pragma unroll
            for (int i = 0; i < 8; i++) rv[i] = fmaxf(fmaf(rv[i], sA8[i], sC8[i]), 0.f);
#pragma unroll
            for (int j = 0; j < 4; j++) {
                int o = ob + j;
                float lg = sB8[o];
#pragma unroll
                for (int i = 0; i < 8; i++) lg = fmaf(rv[i], sW2[i][o], lg);
                wsm[wl][o][pair] = lg;
            }
        }
        // stage neighbor data while logits settle
        stage_nb(sNb[wl], n, lane, knn, U, A0,A1,A2, C0,C1,C2);
        // phase 2: softmax over ns
        if (lane < 8) {
            float* row = wsm[wl][lane];
            float4 v0 = *(float4*)&row[0], v1 = *(float4*)&row[4];
            float4 v2 = *(float4*)&row[8], v3 = *(float4*)&row[12];
            float m = fmaxf(fmaxf(fmaxf(v0.x,v0.y),fmaxf(v0.z,v0.w)),
                     fmaxf(fmaxf(fmaxf(v1.x,v1.y),fmaxf(v1.z,v1.w)),
                     fmaxf(fmaxf(fmaxf(v2.x,v2.y),fmaxf(v2.z,v2.w)),
                           fmaxf(fmaxf(v3.x,v3.y),fmaxf(v3.z,v3.w)))));
            v0.x=__expf(v0.x-m); v0.y=__expf(v0.y-m); v0.z=__expf(v0.z-m); v0.w=__expf(v0.w-m);
            v1.x=__expf(v1.x-m); v1.y=__expf(v1.y-m); v1.z=__expf(v1.z-m); v1.w=__expf(v1.w-m);
            v2.x=__expf(v2.x-m); v2.y=__expf(v2.y-m); v2.z=__expf(v2.z-m); v2.w=__expf(v2.w-m);
            v3.x=__expf(v3.x-m); v3.y=__expf(v3.y-m); v3.z=__expf(v3.z-m); v3.w=__expf(v3.w-m);
            float ssum = (v0.x+v0.y+v0.z+v0.w)+(v1.x+v1.y+v1.z+v1.w)
                        +(v2.x+v2.y+v2.z+v2.w)+(v3.x+v3.y+v3.z+v3.w);
            float inv = 1.f / ssum;
            v0.x*=inv; v0.y*=inv; v0.z*=inv; v0.w*=inv;
            v1.x*=inv; v1.y*=inv; v1.z*=inv; v1.w*=inv;
            v2.x*=inv; v2.y*=inv; v2.z*=inv; v2.w*=inv;
            v3.x*=inv; v3.y*=inv; v3.z*=inv; v3.w*=inv;
            *(float4*)&row[0]=v0; *(float4*)&row[4]=v1;
            *(float4*)&row[8]=v2; *(float4*)&row[12]=v3;
        }
        __syncwarp();
        // phase 3: batched gather + weighted aggregation
        float acc0 = 0.f, acc1 = 0.f;
        const float* wrow = wsm[wl][oo];
#pragma unroll
        for (int nb = 0; nb < 4; nb++) {
            float4 d0 = sNb[wl][nb*4+0];
            float4 d1 = sNb[wl][nb*4+1];
            float4 d2 = sNb[wl][nb*4+2];
            float4 d3 = sNb[wl][nb*4+3];
            float4 wt = *(const float4*)&wrow[nb*4];
            long v0o = (long)__float_as_int(d0.x) * 64;
            long v1o = (long)__float_as_int(d1.x) * 64;
            long v2o = (long)__float_as_int(d2.x) * 64;
            long v3o = (long)__float_as_int(d3.x) * 64;
            float va0 = Vm[v0o+c0], vb0 = Vm[v0o+c1];
            float va1 = Vm[v1o+c0], vb1 = Vm[v1o+c1];
            float va2 = Vm[v2o+c0], vb2 = Vm[v2o+c1];
            float va3 = Vm[v3o+c0], vb3 = Vm[v3o+c1];
            acc0 = fmaf(va0 + fmaf(d0.y,P00,fmaf(d0.z,P10,fmaf(d0.w,P20,B0))), wt.x, acc0);
            acc1 = fmaf(vb0 + fmaf(d0.y,P01,fmaf(d0.z,P11,fmaf(d0.w,P21,B1))), wt.x, acc1);
            acc0 = fmaf(va1 + fmaf(d1.y,P00,fmaf(d1.z,P10,fmaf(d1.w,P20,B0))), wt.y, acc0);
            acc1 = fmaf(vb1 + fmaf(d1.y,P01,fmaf(d1.z,P11,fmaf(d1.w,P21,B1))), wt.y, acc1);
            acc0 = fmaf(va2 + fmaf(d2.y,P00,fmaf(d2.z,P10,fmaf(d2.w,P20,B0))), wt.z, acc0);
            acc1 = fmaf(vb2 + fmaf(d2.y,P01,fmaf(d2.z,P11,fmaf(d2.w,P21,B1))), wt.z, acc1);
            acc0 = fmaf(va3 + fmaf(d3.y,P00,fmaf(d3.z,P10,fmaf(d3.w,P20,B0))), wt.w, acc0);
            acc1 = fmaf(vb3 + fmaf(d3.y,P01,fmaf(d3.z,P11,fmaf(d3.w,P21,B1))), wt.w, acc1);
        }
        agg[(long)n*64 + c0] = acc0;
        agg[(long)n*64 + c1] = acc1;
        s0 += acc0; q0 = fmaf(acc0,acc0,q0);
        s1 += acc1; q1 = fmaf(acc1,acc1,q1);
        __syncwarp();
    }
    atomicAdd(&sS[c0], s0); atomicAdd(&sQ[c0], q0);
    atomicAdd(&sS[c1], s1); atomicAdd(&sQ[c1], q1);
    __syncthreads();
    if (tid < 64) {
        atomicAdd(&st[288 + tid], sS[tid]);
        atomicAdd(&st[352 + tid], sQ[tid]);
    }
}

// ---------------------------------------------------------------------------
// gemm3: t3 = relu(bn2(agg)) @ W3, fused bn3 stats
__global__ void __launch_bounds__(256) k_gemm3(
        const float* __restrict__ X, const float* __restrict__ W,
        const float* __restrict__ st, const float* __restrict__ bg,
        const float* __restrict__ bb, float* __restrict__ out, float* __restrict__ sto)
{
    __shared__ float sX[64][65];
    __shared__ float sW[64][64];
    __shared__ float sA[64], sC[64];
    __shared__ float sS[64], sQ[64];
    const int tid = threadIdx.x;
    const long row0 = (long)blockIdx.x * 64;
    if (tid < 64) {
        sS[tid] = 0.f; sQ[tid] = 0.f;
        float m = st[288 + tid] * INV_N;
        float var = fmaf(-m, m, st[352 + tid] * INV_N);
        float a = bg[tid] * rsqrtf(var + EPSF);
        sA[tid] = a; sC[tid] = fmaf(-m, a, bb[tid]);
    }
    for (int i = tid; i < 4096; i += 256) sW[i >> 6][i & 63] = W[i];
    __syncthreads();
    for (int i = tid; i < 4096; i += 256) {
        int r = i >> 6, kk = i & 63;
        sX[r][kk] = fmaxf(fmaf(X[(row0 + r) * 64 + kk], sA[kk], sC[kk]), 0.f);
    }
    __syncthreads();
    const int lane = tid & 31;
    const int r = tid & 63, c0 = (tid >> 6) << 4;
    float acc[16];
#pragma unroll
    for (int j = 0; j < 16; j++) acc[j] = 0.f;
#pragma unroll
    for (int kk = 0; kk < 64; kk++) {
        float xv = sX[r][kk];
#pragma unroll
        for (int j = 0; j < 16; j++) acc[j] = fmaf(xv, sW[kk][c0 + j], acc[j]);
    }
    float* op = out + (row0 + r) * 64 + c0;
#pragma unroll
    for (int j = 0; j < 16; j++) op[j] = acc[j];
#pragma unroll
    for (int j = 0; j < 16; j++) {
        float s = acc[j], q = acc[j] * acc[j];
#pragma unroll
        for (int off = 16; off; off >>= 1) {
            s += __shfl_xor_sync(0xffffffffu, s, off);
            q += __shfl_xor_sync(0xffffffffu, q, off);
        }
        if (lane == 0) { atomicAdd(&sS[c0 + j], s); atomicAdd(&sQ[c0 + j], q); }
    }
    __syncthreads();
    if (tid < 64) {
        atomicAdd(&sto[416 + tid], sS[tid]);
        atomicAdd(&sto[480 + tid], sQ[tid]);
    }
}

// out = relu(bn3(t3) + x), bn3 params inline
__global__ void k_final(const float* __restrict__ T3, const float* __restrict__ X,
                        const float* __restrict__ st,
                        const float* __restrict__ g3, const float* __restrict__ b3,
                        float* __restrict__ out)
{
    __shared__ float sA[64], sC[64];
    const int tid = threadIdx.x;
    if (tid < 64) {
        float m = st[416 + tid] * INV_N;
        float var = fmaf(-m, m, st[480 + tid] * INV_N);
        float a = g3[tid] * rsqrtf(var + EPSF);
        sA[tid] = a; sC[tid] = fmaf(-m, a, b3[tid]);
    }
    __syncthreads();
    const int stride = gridDim.x * blockDim.x;
    for (int i = blockIdx.x * blockDim.x + tid; i < NPTS * 16; i += stride) {
        int cb = (i * 4) & 63;
        float4 t = ((const float4*)T3)[i];
        float4 x4 = ((const float4*)X)[i];
        float4 r;
        r.x = fmaxf(fmaf(t.x, sA[cb+0], sC[cb+0]) + x4.x, 0.f);
        r.y = fmaxf(fmaf(t.y, sA[cb+1], sC[cb+1]) + x4.y, 0.f);
        r.z = fmaxf(fmaf(t.z, sA[cb+2], sC[cb+2]) + x4.z, 0.f);
        r.w = fmaxf(fmaf(t.w, sA[cb+3], sC[cb+3]) + x4.w, 0.f);
        ((float4*)out)[i] = r;
    }
}

// ---------------------------------------------------------------------------
extern "C" void kernel_launch(void* const* d_in, const int* in_sizes, int n_in,
                              void* d_out, int out_size)
{
    const float* p     = (const float*)d_in[0];
    const float* x     = (const float*)d_in[1];
    const int*   knn   = (const int*)  d_in[2];
    const float* W1    = (const float*)d_in[3];
    const float* bn1g  = (const float*)d_in[4];
    const float* bn1b  = (const float*)d_in[5];
    const float* Wq    = (const float*)d_in[6];
    const float* bq    = (const float*)d_in[7];
    const float* Wk    = (const float*)d_in[8];
    const float* bk    = (const float*)d_in[9];
    const float* Wv    = (const float*)d_in[10];
    const float* bv    = (const float*)d_in[11];
    const float* Wp1   = (const float*)d_in[12];
    const float* bp1   = (const float*)d_in[13];
    const float* bnpg  = (const float*)d_in[14];
    const float* bnpb  = (const float*)d_in[15];
    const float* Wp2   = (const float*)d_in[16];
    const float* bp2   = (const float*)d_in[17];
    const float* bnw1g = (const float*)d_in[18];
    const float* bnw1b = (const float*)d_in[19];
    const float* Ww1   = (const float*)d_in[20];
    const float* bw1   = (const float*)d_in[21];
    const float* bnw2g = (const float*)d_in[22];
    const float* bnw2b = (const float*)d_in[23];
    const float* Ww2   = (const float*)d_in[24];
    const float* bw2   = (const float*)d_in[25];
    const float* bn2g  = (const float*)d_in[26];
    const float* bn2b  = (const float*)d_in[27];
    const float* W3    = (const float*)d_in[28];
    const float* bn3g  = (const float*)d_in[29];
    const float* bn3b  = (const float*)d_in[30];
    float* out = (float*)d_out;

    float* scr = nullptr;
    cudaGetSymbolAddress((void**)&scr, g_scr);
    float* t1  = scr + OFF_T1;
    float* qb  = scr + OFF_Q;
    float* kb  = scr + OFF_K;
    float* vb  = scr + OFF_V;
    float* w1b = scr + OFF_W1B;
    float* agg = scr + OFF_AGG;
    float* t3  = scr + OFF_T3;
    float4* U  = (float4*)(scr + OFF_U);
    float* st  = scr + OFF_STATS;

    k_zero<<<1, 544>>>(st);

    // gemm1 + pstats (heterogeneous grid, overlapped)
    k_g1p<<<GEMM_BLOCKS + PST_BLOCKS, 256>>>(x, W1, t1, st, p, knn, Wp1, bp1, U);

    // q,k,v (bn1 inline)
    k_qkv<<<1250, 256>>>(t1, Wq, bq, Wk, bk, Wv, bv, st, bn1g, bn1b, qb, kb, vb);

    // bnw1 stats
    k_wstats<<<1184, 256>>>(knn, qb, kb, U, bnpg, bnpb, Wp2, bp2, st);

    // pass B (+ bnw2 stats)
    k_passB<<<888, 256>>>(knn, qb, kb, U, bnpg, bnpb, Wp2, bp2,
                          bnw1g, bnw1b, Ww1, bw1, w1b, st);

    // pass C (+ bn2 stats)
    k_passC<<<1184, 256>>>(knn, vb, w1b, U, bnpg, bnpb, Wp2, bp2,
                           bnw2g, bnw2b, Ww2, bw2, agg, st);

    // gemm3 (bn2 inline, + bn3 stats)
    k_gemm3<<<1250, 256>>>(agg, W3, st, bn2g, bn2b, t3, st);

    // residual + relu (bn3 inline)
    k_final<<<640, 256>>>(t3, x, st, bn3g, bn3b, out);
}